// round 1
// baseline (speedup 1.0000x reference)
#include <cuda_runtime.h>
#include <math.h>

#define NSTA 4096
#define NCIT 256
#define NB 8
#define TH 8
#define TP 24
#define TT 32
#define DIN 28
#define DM 27
#define GF 64
#define HH 64
#define NG 192
#define DGRU 92
#define THIST 7
#define NNZMAX (1<<20)

// ---------------- static device scratch ----------------
__device__ float g_dinv_s[NSTA];
__device__ int   g_cnt_s[NSTA];
__device__ int   g_Ls_rowptr[NSTA+1];
__device__ int   g_Ls_cols[NNZMAX];
__device__ float g_Ls_vals[NNZMAX];

__device__ int   g_cnt_afc[NSTA];
__device__ int   g_afc_rowptr[NSTA+1];
__device__ int   g_afc_cols[NNZMAX];

__device__ int   g_cnt_afcT[NCIT];
__device__ int   g_afcT_rowptr[NCIT+1];
__device__ int   g_afcT_cols[NNZMAX];

__device__ float g_dinv_c[NCIT];
__device__ int   g_cnt_c[NCIT];
__device__ float g_Lc[NCIT*NCIT];

__device__ float g_xs [THIST*NB*NSTA*DIN];
__device__ float g_Lxs[THIST*NB*NSTA*DIN];
__device__ float g_xgs[THIST*NB*NSTA*GF];
__device__ float g_tmps[THIST*NB*NSTA*GF];

__device__ float g_xc [THIST*NB*NCIT*DIN];
__device__ float g_Lxc[THIST*NB*NCIT*DIN];
__device__ float g_xgc[THIST*NB*NCIT*GF];
__device__ float g_tmpc[THIST*NB*NCIT*GF];

__device__ float g_hs[NB*NSTA*HH];
__device__ float g_hc[NB*NCIT*HH];
__device__ float g_ys[NB*NSTA];
__device__ float g_yc[NB*NCIT];

// ---------------- preprocessing kernels ----------------

// count nonzeros per row (optionally excluding diagonal); optionally write deg^-0.5
__global__ void k_count_rows(const float* __restrict__ mat, int* __restrict__ cnt,
                             float* __restrict__ dinv, int nrows, int ncols, int excl) {
    int m = blockIdx.x;
    if (m >= nrows) return;
    int c = 0;
    for (int j = threadIdx.x; j < ncols; j += blockDim.x) {
        float v = mat[(size_t)m*ncols + j];
        if (v != 0.f && !(excl && j == m)) c++;
    }
    __shared__ int sred[128];
    sred[threadIdx.x] = c; __syncthreads();
    for (int s = 64; s > 0; s >>= 1) {
        if (threadIdx.x < s) sred[threadIdx.x] += sred[threadIdx.x + s];
        __syncthreads();
    }
    if (threadIdx.x == 0) {
        cnt[m] = sred[0];
        if (dinv) dinv[m] = (sred[0] > 0) ? rsqrtf((float)sred[0]) : 0.f;
    }
}

// count nonzeros per column (for afc^T)
__global__ void k_count_cols(const float* __restrict__ mat, int* __restrict__ cnt,
                             int nrows, int ncols) {
    int c = blockIdx.x;
    if (c >= ncols) return;
    int acc = 0;
    for (int s = threadIdx.x; s < nrows; s += blockDim.x)
        if (mat[(size_t)s*ncols + c] != 0.f) acc++;
    __shared__ int sred[128];
    sred[threadIdx.x] = acc; __syncthreads();
    for (int s = 64; s > 0; s >>= 1) {
        if (threadIdx.x < s) sred[threadIdx.x] += sred[threadIdx.x + s];
        __syncthreads();
    }
    if (threadIdx.x == 0) cnt[c] = sred[0];
}

// single-block exclusive scan (n <= 4096, blockDim = 1024)
__global__ void k_scan(const int* __restrict__ cnt, int* __restrict__ rowptr, int n) {
    __shared__ int s[1024];
    int tid = threadIdx.x;
    int per = (n + 1023) / 1024;
    int base = tid * per;
    int loc = 0;
    for (int i = 0; i < per; i++) if (base + i < n) loc += cnt[base + i];
    s[tid] = loc; __syncthreads();
    for (int off = 1; off < 1024; off <<= 1) {
        int v = (tid >= off) ? s[tid - off] : 0;
        __syncthreads();
        s[tid] += v;
        __syncthreads();
    }
    int a = (tid == 0) ? 0 : s[tid - 1];
    for (int i = 0; i < per; i++) {
        if (base + i < n) { rowptr[base + i] = a; a += cnt[base + i]; }
    }
    if (tid == 1023) rowptr[n] = a;
}

// warp-per-row ordered CSR fill; vals = -dinv[m]*dinv[j] when vals != null
__global__ void k_fill_csr(const float* __restrict__ mat, const int* __restrict__ rowptr,
                           int* __restrict__ cols, float* __restrict__ vals,
                           const float* __restrict__ dinv,
                           int nrows, int ncols, int excl) {
    int m = blockIdx.x * (blockDim.x / 32) + (threadIdx.x / 32);
    if (m >= nrows) return;
    int lane = threadIdx.x & 31;
    int pos = rowptr[m];
    float dm = dinv ? dinv[m] : 0.f;
    for (int base = 0; base < ncols; base += 32) {
        int j = base + lane;
        bool p = (j < ncols) && (mat[(size_t)m*ncols + j] != 0.f) && !(excl && j == m);
        unsigned msk = __ballot_sync(0xffffffffu, p);
        if (p) {
            int off = __popc(msk & ((1u << lane) - 1u));
            cols[pos + off] = j;
            if (vals) vals[pos + off] = -dm * dinv[j];
        }
        pos += __popc(msk);
    }
}

// warp-per-column CSR fill of the transpose (cols only, values are 1)
__global__ void k_fill_csrT(const float* __restrict__ mat, const int* __restrict__ rowptr,
                            int* __restrict__ cols, int nrows, int ncols) {
    int c = blockIdx.x * (blockDim.x / 32) + (threadIdx.x / 32);
    if (c >= ncols) return;
    int lane = threadIdx.x & 31;
    int pos = rowptr[c];
    for (int base = 0; base < nrows; base += 32) {
        int s = base + lane;
        bool p = (s < nrows) && (mat[(size_t)s*ncols + c] != 0.f);
        unsigned msk = __ballot_sync(0xffffffffu, p);
        if (p) cols[pos + __popc(msk & ((1u << lane) - 1u))] = s;
        pos += __popc(msk);
    }
}

__global__ void k_fill_Lc(const float* __restrict__ adj) {
    int m = blockIdx.x, n = threadIdx.x;
    float v = 0.f;
    if (n != m && adj[m*NCIT + n] != 0.f) v = -g_dinv_c[m] * g_dinv_c[n];
    g_Lc[m*NCIT + n] = v;
}

// ---------------- data staging ----------------

// history inputs: x_all[t,b,n,:] = [x_hist[b,t,n,0], features[b,t+1,n,:]]
__global__ void k_build_hist_x(const float* __restrict__ xh_s, const float* __restrict__ ft_s,
                               const float* __restrict__ xh_c, const float* __restrict__ ft_c) {
    int i = blockIdx.x * blockDim.x + threadIdx.x;
    const int nS = THIST*NB*NSTA*DIN;
    const int nC = THIST*NB*NCIT*DIN;
    if (i < nS) {
        int ch = i % DIN; int r = i / DIN; int n = r % NSTA; int tb = r / NSTA;
        int b = tb % NB; int t = tb / NB;
        float v;
        if (ch == 0) v = xh_s[(b*TH + t)*NSTA + n];
        else v = ft_s[((b*TT + (t+1))*NSTA + n)*DM + (ch-1)];
        g_xs[i] = v;
    } else if (i < nS + nC) {
        int k = i - nS;
        int ch = k % DIN; int r = k / DIN; int n = r % NCIT; int tb = r / NCIT;
        int b = tb % NB; int t = tb / NB;
        float v;
        if (ch == 0) v = xh_c[(b*TH + t)*NCIT + n];
        else v = ft_c[((b*TT + (t+1))*NCIT + n)*DM + (ch-1)];
        g_xc[k] = v;
    }
}

// pred inputs: x[b,n,:] = [y_prev[b,n], features[b,tt,n,:]]
__global__ void k_build_pred_x(const float* __restrict__ ft_s, const float* __restrict__ ft_c, int tt) {
    int i = blockIdx.x * blockDim.x + threadIdx.x;
    const int nS = NB*NSTA*DIN;
    const int nC = NB*NCIT*DIN;
    if (i < nS) {
        int ch = i % DIN; int r = i / DIN; int n = r % NSTA; int b = r / NSTA;
        g_xs[i] = (ch == 0) ? g_ys[r] : ft_s[((b*TT + tt)*NSTA + n)*DM + (ch-1)];
    } else if (i < nS + nC) {
        int k = i - nS;
        int ch = k % DIN; int r = k / DIN; int n = r % NCIT; int b = r / NCIT;
        g_xc[k] = (ch == 0) ? g_yc[r] : ft_c[((b*TT + tt)*NCIT + n)*DM + (ch-1)];
    }
}

__global__ void k_init_y(const float* __restrict__ xh_s, const float* __restrict__ xh_c) {
    int i = blockIdx.x * blockDim.x + threadIdx.x;
    if (i < NB*NSTA) {
        int b = i / NSTA, n = i % NSTA;
        g_ys[i] = xh_s[(b*TH + (TH-1))*NSTA + n];
    } else if (i < NB*NSTA + NB*NCIT) {
        int k = i - NB*NSTA;
        int b = k / NCIT, n = k % NCIT;
        g_yc[k] = xh_c[(b*TH + (TH-1))*NCIT + n];
    }
}

__global__ void k_zero_h() {
    int i = blockIdx.x * blockDim.x + threadIdx.x;
    if (i < NB*NSTA*HH) g_hs[i] = 0.f;
    else if (i < NB*NSTA*HH + NB*NCIT*HH) g_hc[i - NB*NSTA*HH] = 0.f;
}

// ---------------- L apply ----------------

// sparse L_s @ x : one warp per (row, tb); grid = (NSTA, ntb)
__global__ void k_spmm(const float* __restrict__ x, float* __restrict__ out) {
    int m = blockIdx.x;
    int tb = blockIdx.y;
    int lane = threadIdx.x;
    int beg = g_Ls_rowptr[m], end = g_Ls_rowptr[m+1];
    const float* xb = x + (size_t)tb * NSTA * DIN;
    if (lane < DIN) {
        float acc = 0.f;
        for (int p = beg; p < end; p++)
            acc += g_Ls_vals[p] * xb[g_Ls_cols[p]*DIN + lane];
        out[((size_t)tb*NSTA + m)*DIN + lane] = acc;
    }
}

// dense L_c @ x
__global__ void k_lmm_c(const float* __restrict__ x, float* __restrict__ out, int ntb) {
    int i = blockIdx.x * blockDim.x + threadIdx.x;
    int total = ntb * NCIT * DIN;
    if (i >= total) return;
    int ch = i % DIN; int r = i / DIN; int m = r % NCIT; int tb = r / NCIT;
    const float* xb = x + (size_t)tb * NCIT * DIN;
    float acc = 0.f;
    for (int n2 = 0; n2 < NCIT; n2++) acc += g_Lc[m*NCIT + n2] * xb[n2*DIN + ch];
    out[i] = acc;
}

// ---------------- Cheb conv: out = sigmoid(x@W0 + Lx@W1 + b) ----------------
__global__ void k_cheb(const float* __restrict__ xS, const float* __restrict__ lxS,
                       const float* __restrict__ wS, const float* __restrict__ bS,
                       float* __restrict__ outS, int nrowsS,
                       const float* __restrict__ xC, const float* __restrict__ lxC,
                       const float* __restrict__ wC, const float* __restrict__ bC,
                       float* __restrict__ outC, int nrowsC, int nblkS) {
    __shared__ float sW[2*DIN*GF];
    __shared__ float sB[GF];
    __shared__ float sx[4][DIN];
    __shared__ float slx[4][DIN];
    const float *x, *lx, *w, *bias; float* out; int nrows, blkid, nblk;
    if ((int)blockIdx.x < nblkS) { x=xS; lx=lxS; w=wS; bias=bS; out=outS; nrows=nrowsS; blkid=blockIdx.x; nblk=nblkS; }
    else { x=xC; lx=lxC; w=wC; bias=bC; out=outC; nrows=nrowsC; blkid=blockIdx.x - nblkS; nblk=gridDim.x - nblkS; }
    int tid = threadIdx.x;  // 64
    for (int i = tid; i < 2*DIN*GF; i += 64) sW[i] = w[i];
    if (tid < GF) sB[tid] = bias[tid];
    __syncthreads();
    for (long r0 = (long)blkid*4; r0 < nrows; r0 += (long)nblk*4) {
        int nr = (int)min((long)4, (long)nrows - r0);
        for (int i = tid; i < nr*DIN; i += 64) {
            int rr = i / DIN, ch = i % DIN;
            sx[rr][ch]  = x [(r0+rr)*DIN + ch];
            slx[rr][ch] = lx[(r0+rr)*DIN + ch];
        }
        __syncthreads();
        float acc[4];
        #pragma unroll
        for (int rr = 0; rr < 4; rr++) acc[rr] = sB[tid];
        for (int ch = 0; ch < DIN; ch++) {
            float w0 = sW[ch*GF + tid];
            float w1 = sW[DIN*GF + ch*GF + tid];
            #pragma unroll
            for (int rr = 0; rr < 4; rr++)
                acc[rr] += sx[rr][ch]*w0 + slx[rr][ch]*w1;
        }
        for (int rr = 0; rr < nr; rr++)
            out[(r0+rr)*GF + tid] = 1.f / (1.f + __expf(-acc[rr]));
        __syncthreads();
    }
}

// ---------------- fuse gather: tmp = A @ xg (sparse binary) ----------------
__global__ void k_gather(const float* __restrict__ xgS, const float* __restrict__ xgC,
                         float* __restrict__ tmpS, float* __restrict__ tmpC, int ntb) {
    int i = blockIdx.x * blockDim.x + threadIdx.x;
    const int nSel = ntb * NSTA * GF;
    const int nCel = ntb * NCIT * GF;
    if (i < nSel) {
        int g = i % GF; int r = i / GF; int s = r % NSTA; int tb = r / NSTA;
        int beg = g_afc_rowptr[s], end = g_afc_rowptr[s+1];
        const float* xb = xgC + (size_t)tb * NCIT * GF;
        float acc = 0.f;
        for (int p = beg; p < end; p++) acc += xb[g_afc_cols[p]*GF + g];
        tmpS[i] = acc;
    } else if (i < nSel + nCel) {
        int k = i - nSel;
        int g = k % GF; int r = k / GF; int c = r % NCIT; int tb = r / NCIT;
        int beg = g_afcT_rowptr[c], end = g_afcT_rowptr[c+1];
        const float* xb = xgS + (size_t)tb * NSTA * GF;
        float acc = 0.f;
        for (int p = beg; p < end; p++) acc += xb[g_afcT_cols[p]*GF + g];
        tmpC[k] = acc;
    }
}

// ---------------- fuse apply: xg += tmp @ W + b ----------------
__global__ void k_apply(float* __restrict__ xgS, const float* __restrict__ tmpS,
                        const float* __restrict__ wS, const float* __restrict__ bS, int nrowsS,
                        float* __restrict__ xgC, const float* __restrict__ tmpC,
                        const float* __restrict__ wC, const float* __restrict__ bC, int nrowsC,
                        int nblkS) {
    __shared__ float sW[GF*GF];
    __shared__ float sB[GF];
    __shared__ float st[4][GF];
    float* xg; const float *tmp, *w, *bias; int nrows, blkid, nblk;
    if ((int)blockIdx.x < nblkS) { xg=xgS; tmp=tmpS; w=wS; bias=bS; nrows=nrowsS; blkid=blockIdx.x; nblk=nblkS; }
    else { xg=xgC; tmp=tmpC; w=wC; bias=bC; nrows=nrowsC; blkid=blockIdx.x - nblkS; nblk=gridDim.x - nblkS; }
    int tid = threadIdx.x;  // 64
    for (int i = tid; i < GF*GF; i += 64) sW[i] = w[i];
    if (tid < GF) sB[tid] = bias[tid];
    __syncthreads();
    for (long r0 = (long)blkid*4; r0 < nrows; r0 += (long)nblk*4) {
        int nr = (int)min((long)4, (long)nrows - r0);
        for (int i = tid; i < nr*GF; i += 64) {
            int rr = i / GF, ch = i % GF;
            st[rr][ch] = tmp[(r0+rr)*GF + ch];
        }
        __syncthreads();
        float acc[4];
        #pragma unroll
        for (int rr = 0; rr < 4; rr++) acc[rr] = sB[tid];
        for (int ch = 0; ch < GF; ch++) {
            float wv = sW[ch*GF + tid];
            #pragma unroll
            for (int rr = 0; rr < 4; rr++) acc[rr] += st[rr][ch]*wv;
        }
        for (int rr = 0; rr < nr; rr++)
            xg[(r0+rr)*GF + tid] += acc[rr];
        __syncthreads();
    }
}

// ---------------- GRU step (+optional fc head) ----------------
// 192 threads, one gate column per thread, 2 rows per iteration.
__global__ void k_gru(const float* __restrict__ xa, const float* __restrict__ xgf,
                      float* __restrict__ h,
                      const float* __restrict__ wi, const float* __restrict__ wh,
                      const float* __restrict__ bi, const float* __restrict__ bh,
                      int nrows, int idx,
                      const float* __restrict__ fcw, const float* __restrict__ fcb,
                      float* __restrict__ ybuf, float* __restrict__ yout,
                      int step, int nnodes) {
    __shared__ float sx[2][DGRU];
    __shared__ float sh[2][HH];
    __shared__ float sgi[2][NG];
    __shared__ float sgh[2][NG];
    int tid = threadIdx.x;  // 192
    for (long r0 = (long)blockIdx.x*2; r0 < nrows; r0 += (long)gridDim.x*2) {
        int nr = (r0 + 1 < nrows) ? 2 : 1;
        for (int rr = 0; rr < nr; rr++) {
            long r = r0 + rr;
            if (tid < DIN) sx[rr][tid] = xa[r*DIN + tid];
            else if (tid < DGRU) sx[rr][tid] = xgf[r*GF + (tid - DIN)];
            else if (tid < DGRU + HH) sh[rr][tid - DGRU] = h[r*HH + (tid - DGRU)];
        }
        __syncthreads();
        float a0 = bi[tid], a1 = a0;
        for (int ch = 0; ch < DGRU; ch++) {
            float w = wi[ch*NG + tid];
            a0 += w * sx[0][ch];
            a1 += w * sx[1][ch];
        }
        float b0 = bh[tid], b1 = b0;
        for (int k = 0; k < HH; k++) {
            float w = wh[k*NG + tid];
            b0 += w * sh[0][k];
            b1 += w * sh[1][k];
        }
        sgi[0][tid] = a0; sgi[1][tid] = a1;
        sgh[0][tid] = b0; sgh[1][tid] = b1;
        __syncthreads();
        if (tid < HH) {
            int j = tid;
            int interval = 1 << (j >> 4);
            bool upd = (idx % interval) == 0;
            for (int rr = 0; rr < nr; rr++) {
                long r = r0 + rr;
                float hold = sh[rr][j];
                float rg = 1.f / (1.f + __expf(-(sgi[rr][j]       + sgh[rr][j])));
                float z  = 1.f / (1.f + __expf(-(sgi[rr][HH+j]    + sgh[rr][HH+j])));
                float nn = tanhf(sgi[rr][2*HH+j] + rg * sgh[rr][2*HH+j]);
                float hn = (1.f - z)*nn + z*hold;
                float hf = upd ? hn : hold;
                h[r*HH + j] = hf;
                if (yout) sgi[rr][j] = hf * fcw[j];
            }
        }
        __syncthreads();
        if (yout && tid < nr) {
            int rr = tid;
            long r = r0 + rr;
            float s = 0.f;
            for (int j = 0; j < HH; j++) s += sgi[rr][j];
            s += fcb[0];
            ybuf[r] = s;
            int b = (int)(r / nnodes);
            int n = (int)(r % nnodes);
            yout[((size_t)b*TP + step)*nnodes + n] = s;
        }
        __syncthreads();
    }
}

// ---------------- host ----------------
static void* symaddr(const void* sym) {
    void* p = nullptr;
    cudaGetSymbolAddress(&p, sym);
    return p;
}

extern "C" void kernel_launch(void* const* d_in, const int* in_sizes, int n_in,
                              void* d_out, int out_size) {
    const float* x_hist     = (const float*)d_in[0];
    const float* features   = (const float*)d_in[1];
    const float* c_x_hist   = (const float*)d_in[2];
    const float* c_features = (const float*)d_in[3];
    const float* adj_sta    = (const float*)d_in[4];
    const float* adj_city   = (const float*)d_in[5];
    const float* afc        = (const float*)d_in[6];
    const float* conv_w     = (const float*)d_in[7];
    const float* conv_b     = (const float*)d_in[8];
    const float* c_conv_w   = (const float*)d_in[9];
    const float* c_conv_b   = (const float*)d_in[10];
    const float* gru_wi     = (const float*)d_in[11];
    const float* gru_wh     = (const float*)d_in[12];
    const float* gru_bi     = (const float*)d_in[13];
    const float* gru_bh     = (const float*)d_in[14];
    const float* c_gru_wi   = (const float*)d_in[15];
    const float* c_gru_wh   = (const float*)d_in[16];
    const float* c_gru_bi   = (const float*)d_in[17];
    const float* c_gru_bh   = (const float*)d_in[18];
    const float* fc_w       = (const float*)d_in[19];
    const float* fc_b       = (const float*)d_in[20];
    const float* c_fc_w     = (const float*)d_in[21];
    const float* c_fc_b     = (const float*)d_in[22];
    const float* c2s_w      = (const float*)d_in[23];
    const float* c2s_b      = (const float*)d_in[24];
    const float* s2c_w      = (const float*)d_in[25];
    const float* s2c_b      = (const float*)d_in[26];

    float* out_s = (float*)d_out;
    float* out_c = out_s + (size_t)NB * TP * NSTA;

    float* p_dinv_s     = (float*)symaddr(g_dinv_s);
    int*   p_cnt_s      = (int*)  symaddr(g_cnt_s);
    int*   p_Ls_rowptr  = (int*)  symaddr(g_Ls_rowptr);
    int*   p_Ls_cols    = (int*)  symaddr(g_Ls_cols);
    float* p_Ls_vals    = (float*)symaddr(g_Ls_vals);
    int*   p_cnt_afc    = (int*)  symaddr(g_cnt_afc);
    int*   p_afc_rowptr = (int*)  symaddr(g_afc_rowptr);
    int*   p_afc_cols   = (int*)  symaddr(g_afc_cols);
    int*   p_cnt_afcT   = (int*)  symaddr(g_cnt_afcT);
    int*   p_afcT_rowptr= (int*)  symaddr(g_afcT_rowptr);
    int*   p_afcT_cols  = (int*)  symaddr(g_afcT_cols);
    float* p_dinv_c     = (float*)symaddr(g_dinv_c);
    int*   p_cnt_c      = (int*)  symaddr(g_cnt_c);
    float* p_xs   = (float*)symaddr(g_xs);
    float* p_Lxs  = (float*)symaddr(g_Lxs);
    float* p_xgs  = (float*)symaddr(g_xgs);
    float* p_tmps = (float*)symaddr(g_tmps);
    float* p_xc   = (float*)symaddr(g_xc);
    float* p_Lxc  = (float*)symaddr(g_Lxc);
    float* p_xgc  = (float*)symaddr(g_xgc);
    float* p_tmpc = (float*)symaddr(g_tmpc);
    float* p_hs   = (float*)symaddr(g_hs);
    float* p_hc   = (float*)symaddr(g_hc);
    float* p_ys   = (float*)symaddr(g_ys);
    float* p_yc   = (float*)symaddr(g_yc);

    (void)in_sizes; (void)n_in; (void)out_size;

    // ---- preprocessing: Laplacians + CSR structures ----
    k_count_rows<<<NSTA, 128>>>(adj_sta, p_cnt_s, p_dinv_s, NSTA, NSTA, 1);
    k_scan<<<1, 1024>>>(p_cnt_s, p_Ls_rowptr, NSTA);
    k_fill_csr<<<(NSTA+3)/4, 128>>>(adj_sta, p_Ls_rowptr, p_Ls_cols, p_Ls_vals, p_dinv_s, NSTA, NSTA, 1);

    k_count_rows<<<NSTA, 128>>>(afc, p_cnt_afc, nullptr, NSTA, NCIT, 0);
    k_scan<<<1, 1024>>>(p_cnt_afc, p_afc_rowptr, NSTA);
    k_fill_csr<<<(NSTA+3)/4, 128>>>(afc, p_afc_rowptr, p_afc_cols, nullptr, nullptr, NSTA, NCIT, 0);

    k_count_cols<<<NCIT, 128>>>(afc, p_cnt_afcT, NSTA, NCIT);
    k_scan<<<1, 1024>>>(p_cnt_afcT, p_afcT_rowptr, NCIT);
    k_fill_csrT<<<(NCIT+3)/4, 128>>>(afc, p_afcT_rowptr, p_afcT_cols, NSTA, NCIT);

    k_count_rows<<<NCIT, 128>>>(adj_city, p_cnt_c, p_dinv_c, NCIT, NCIT, 1);
    k_fill_Lc<<<NCIT, NCIT>>>(adj_city);

    // ---- history (batched over 7 steps) ----
    {
        int tot = THIST*NB*NSTA*DIN + THIST*NB*NCIT*DIN;
        k_build_hist_x<<<(tot+255)/256, 256>>>(x_hist, features, c_x_hist, c_features);
    }
    k_spmm<<<dim3(NSTA, THIST*NB), 32>>>(p_xs, p_Lxs);
    k_lmm_c<<<(THIST*NB*NCIT*DIN+255)/256, 256>>>(p_xc, p_Lxc, THIST*NB);
    k_cheb<<<2048+128, 64>>>(p_xs, p_Lxs, conv_w, conv_b, p_xgs, THIST*NB*NSTA,
                             p_xc, p_Lxc, c_conv_w, c_conv_b, p_xgc, THIST*NB*NCIT, 2048);
    {
        int tot = THIST*NB*NSTA*GF + THIST*NB*NCIT*GF;
        k_gather<<<(tot+255)/256, 256>>>(p_xgs, p_xgc, p_tmps, p_tmpc, THIST*NB);
    }
    k_apply<<<2048+128, 64>>>(p_xgs, p_tmps, c2s_w, c2s_b, THIST*NB*NSTA,
                              p_xgc, p_tmpc, s2c_w, s2c_b, THIST*NB*NCIT, 2048);
    {
        int tot = NB*NSTA*HH + NB*NCIT*HH;
        k_zero_h<<<(tot+255)/256, 256>>>();
    }
    for (int t = 0; t < THIST; t++) {
        k_gru<<<2048, 192>>>(p_xs + (size_t)t*NB*NSTA*DIN, p_xgs + (size_t)t*NB*NSTA*GF, p_hs,
                             gru_wi, gru_wh, gru_bi, gru_bh, NB*NSTA, 1+t,
                             nullptr, nullptr, nullptr, nullptr, 0, NSTA);
        k_gru<<<512, 192>>>(p_xc + (size_t)t*NB*NCIT*DIN, p_xgc + (size_t)t*NB*NCIT*GF, p_hc,
                            c_gru_wi, c_gru_wh, c_gru_bi, c_gru_bh, NB*NCIT, 1+t,
                            nullptr, nullptr, nullptr, nullptr, 0, NCIT);
    }
    {
        int tot = NB*NSTA + NB*NCIT;
        k_init_y<<<(tot+255)/256, 256>>>(x_hist, c_x_hist);
    }

    // ---- autoregressive prediction (24 steps) ----
    for (int s = 0; s < TP; s++) {
        int tt = TH + s;
        int idx = TH + s;
        {
            int tot = NB*NSTA*DIN + NB*NCIT*DIN;
            k_build_pred_x<<<(tot+255)/256, 256>>>(features, c_features, tt);
        }
        k_spmm<<<dim3(NSTA, NB), 32>>>(p_xs, p_Lxs);
        k_lmm_c<<<(NB*NCIT*DIN+255)/256, 256>>>(p_xc, p_Lxc, NB);
        k_cheb<<<1024+64, 64>>>(p_xs, p_Lxs, conv_w, conv_b, p_xgs, NB*NSTA,
                                p_xc, p_Lxc, c_conv_w, c_conv_b, p_xgc, NB*NCIT, 1024);
        {
            int tot = NB*NSTA*GF + NB*NCIT*GF;
            k_gather<<<(tot+255)/256, 256>>>(p_xgs, p_xgc, p_tmps, p_tmpc, NB);
        }
        k_apply<<<1024+64, 64>>>(p_xgs, p_tmps, c2s_w, c2s_b, NB*NSTA,
                                 p_xgc, p_tmpc, s2c_w, s2c_b, NB*NCIT, 1024);
        k_gru<<<2048, 192>>>(p_xs, p_xgs, p_hs, gru_wi, gru_wh, gru_bi, gru_bh,
                             NB*NSTA, idx, fc_w, fc_b, p_ys, out_s, s, NSTA);
        k_gru<<<512, 192>>>(p_xc, p_xgc, p_hc, c_gru_wi, c_gru_wh, c_gru_bi, c_gru_bh,
                            NB*NCIT, idx, c_fc_w, c_fc_b, p_yc, out_c, s, NCIT);
    }
}

// round 2
// speedup vs baseline: 1.2503x; 1.2503x over previous
#include <cuda_runtime.h>
#include <math.h>

#define NSTA 4096
#define NCIT 256
#define NB 8
#define TH 8
#define TP 24
#define TT 32
#define DIN 28
#define DM 27
#define GF 64
#define HH 64
#define NG 192
#define DGRU 92
#define THIST 7
#define NNZMAX (1<<20)

#define NBLK_S 128
#define NBLK_C 20
#define GRU_GRID (NBLK_S + NBLK_C)

typedef unsigned long long ull;

// ---------------- static device scratch ----------------
__device__ float g_dinv_s[NSTA];
__device__ int   g_cnt_s[NSTA];
__device__ int   g_Ls_rowptr[NSTA+1];
__device__ int   g_Ls_cols[NNZMAX];
__device__ float g_Ls_vals[NNZMAX];

__device__ int   g_cnt_afc[NSTA];
__device__ int   g_afc_rowptr[NSTA+1];
__device__ int   g_afc_cols[NNZMAX];

__device__ int   g_cnt_afcT[NCIT];
__device__ int   g_afcT_rowptr[NCIT+1];
__device__ int   g_afcT_cols[NNZMAX];

__device__ float g_dinv_c[NCIT];
__device__ int   g_cnt_c[NCIT];
__device__ float g_Lc[NCIT*NCIT];

__device__ float g_xs [THIST*NB*NSTA*DIN];
__device__ float g_Lxs[THIST*NB*NSTA*DIN];
__device__ float g_xgs[THIST*NB*NSTA*GF];
__device__ float g_fxs[THIST*NB*NSTA*GF];

__device__ float g_xc [THIST*NB*NCIT*DIN];
__device__ float g_Lxc[THIST*NB*NCIT*DIN];
__device__ float g_xgc[THIST*NB*NCIT*GF];
__device__ float g_fxc[THIST*NB*NCIT*GF];

__device__ float g_hs[NB*NSTA*HH];
__device__ float g_hc[NB*NCIT*HH];
__device__ float g_ys[NB*NSTA];
__device__ float g_yc[NB*NCIT];

// ---------------- f32x2 helpers ----------------
__device__ __forceinline__ ull splat2(float w) {
    ull r;
    asm("mov.b64 %0, {%1, %1};" : "=l"(r) : "f"(w));
    return r;
}
__device__ __forceinline__ void fma2(ull& a, ull x, ull w) {
    asm("fma.rn.f32x2 %0, %1, %2, %0;" : "+l"(a) : "l"(x), "l"(w));
}
__device__ __forceinline__ float2 unp2(ull v) {
    float2 f;
    asm("mov.b64 {%0, %1}, %2;" : "=f"(f.x), "=f"(f.y) : "l"(v));
    return f;
}
__device__ __forceinline__ float sigm(float x) { return 1.f / (1.f + __expf(-x)); }

// ---------------- preprocessing kernels ----------------
__global__ void k_count_rows(const float* __restrict__ mat, int* __restrict__ cnt,
                             float* __restrict__ dinv, int nrows, int ncols, int excl) {
    int m = blockIdx.x;
    if (m >= nrows) return;
    int c = 0;
    for (int j = threadIdx.x; j < ncols; j += blockDim.x) {
        float v = mat[(size_t)m*ncols + j];
        if (v != 0.f && !(excl && j == m)) c++;
    }
    __shared__ int sred[128];
    sred[threadIdx.x] = c; __syncthreads();
    for (int s = 64; s > 0; s >>= 1) {
        if (threadIdx.x < s) sred[threadIdx.x] += sred[threadIdx.x + s];
        __syncthreads();
    }
    if (threadIdx.x == 0) {
        cnt[m] = sred[0];
        if (dinv) dinv[m] = (sred[0] > 0) ? rsqrtf((float)sred[0]) : 0.f;
    }
}

__global__ void k_count_cols(const float* __restrict__ mat, int* __restrict__ cnt,
                             int nrows, int ncols) {
    int c = blockIdx.x;
    if (c >= ncols) return;
    int acc = 0;
    for (int s = threadIdx.x; s < nrows; s += blockDim.x)
        if (mat[(size_t)s*ncols + c] != 0.f) acc++;
    __shared__ int sred[128];
    sred[threadIdx.x] = acc; __syncthreads();
    for (int s = 64; s > 0; s >>= 1) {
        if (threadIdx.x < s) sred[threadIdx.x] += sred[threadIdx.x + s];
        __syncthreads();
    }
    if (threadIdx.x == 0) cnt[c] = sred[0];
}

__global__ void k_scan(const int* __restrict__ cnt, int* __restrict__ rowptr, int n) {
    __shared__ int s[1024];
    int tid = threadIdx.x;
    int per = (n + 1023) / 1024;
    int base = tid * per;
    int loc = 0;
    for (int i = 0; i < per; i++) if (base + i < n) loc += cnt[base + i];
    s[tid] = loc; __syncthreads();
    for (int off = 1; off < 1024; off <<= 1) {
        int v = (tid >= off) ? s[tid - off] : 0;
        __syncthreads();
        s[tid] += v;
        __syncthreads();
    }
    int a = (tid == 0) ? 0 : s[tid - 1];
    for (int i = 0; i < per; i++) {
        if (base + i < n) { rowptr[base + i] = a; a += cnt[base + i]; }
    }
    if (tid == 1023) rowptr[n] = a;
}

__global__ void k_fill_csr(const float* __restrict__ mat, const int* __restrict__ rowptr,
                           int* __restrict__ cols, float* __restrict__ vals,
                           const float* __restrict__ dinv,
                           int nrows, int ncols, int excl) {
    int m = blockIdx.x * (blockDim.x / 32) + (threadIdx.x / 32);
    if (m >= nrows) return;
    int lane = threadIdx.x & 31;
    int pos = rowptr[m];
    float dm = dinv ? dinv[m] : 0.f;
    for (int base = 0; base < ncols; base += 32) {
        int j = base + lane;
        bool p = (j < ncols) && (mat[(size_t)m*ncols + j] != 0.f) && !(excl && j == m);
        unsigned msk = __ballot_sync(0xffffffffu, p);
        if (p) {
            int off = __popc(msk & ((1u << lane) - 1u));
            cols[pos + off] = j;
            if (vals) vals[pos + off] = -dm * dinv[j];
        }
        pos += __popc(msk);
    }
}

__global__ void k_fill_csrT(const float* __restrict__ mat, const int* __restrict__ rowptr,
                            int* __restrict__ cols, int nrows, int ncols) {
    int c = blockIdx.x * (blockDim.x / 32) + (threadIdx.x / 32);
    if (c >= ncols) return;
    int lane = threadIdx.x & 31;
    int pos = rowptr[c];
    for (int base = 0; base < nrows; base += 32) {
        int s = base + lane;
        bool p = (s < nrows) && (mat[(size_t)s*ncols + c] != 0.f);
        unsigned msk = __ballot_sync(0xffffffffu, p);
        if (p) cols[pos + __popc(msk & ((1u << lane) - 1u))] = s;
        pos += __popc(msk);
    }
}

__global__ void k_fill_Lc(const float* __restrict__ adj) {
    int m = blockIdx.x, n = threadIdx.x;
    float v = 0.f;
    if (n != m && adj[m*NCIT + n] != 0.f) v = -g_dinv_c[m] * g_dinv_c[n];
    g_Lc[m*NCIT + n] = v;
}

// ---------------- history staging ----------------
__global__ void k_build_hist_x(const float* __restrict__ xh_s, const float* __restrict__ ft_s,
                               const float* __restrict__ xh_c, const float* __restrict__ ft_c) {
    int i = blockIdx.x * blockDim.x + threadIdx.x;
    const int nS = THIST*NB*NSTA*DIN;
    const int nC = THIST*NB*NCIT*DIN;
    if (i < nS) {
        int ch = i % DIN; int r = i / DIN; int n = r % NSTA; int tb = r / NSTA;
        int b = tb % NB; int t = tb / NB;
        float v;
        if (ch == 0) v = xh_s[(b*TH + t)*NSTA + n];
        else v = ft_s[((b*TT + (t+1))*NSTA + n)*DM + (ch-1)];
        g_xs[i] = v;
    } else if (i < nS + nC) {
        int k = i - nS;
        int ch = k % DIN; int r = k / DIN; int n = r % NCIT; int tb = r / NCIT;
        int b = tb % NB; int t = tb / NB;
        float v;
        if (ch == 0) v = xh_c[(b*TH + t)*NCIT + n];
        else v = ft_c[((b*TT + (t+1))*NCIT + n)*DM + (ch-1)];
        g_xc[k] = v;
    }
}

// sparse L_s @ x (history; reads g_xs). warp per (m, tb), 4 warps/block.
__global__ void k_spmm_hist(int ntb) {
    int wid = blockIdx.x * 4 + (threadIdx.x >> 5);
    int lane = threadIdx.x & 31;
    if (wid >= NSTA * ntb) return;
    int m = wid / ntb;
    int tb = wid % ntb;
    int beg = g_Ls_rowptr[m], end = g_Ls_rowptr[m+1];
    const float* xb = g_xs + (size_t)tb * NSTA * DIN;
    if (lane < DIN) {
        float acc = 0.f;
        for (int p = beg; p < end; p++)
            acc += g_Ls_vals[p] * xb[g_Ls_cols[p]*DIN + lane];
        g_Lxs[((size_t)tb*NSTA + m)*DIN + lane] = acc;
    }
}

__global__ void k_lmm_hist(int ntb) {
    int i = blockIdx.x * blockDim.x + threadIdx.x;
    int total = ntb * NCIT * DIN;
    if (i >= total) return;
    int ch = i % DIN; int r = i / DIN; int m = r % NCIT; int tb = r / NCIT;
    const float* xb = g_xc + (size_t)tb * NCIT * DIN;
    float acc = 0.f;
    for (int n2 = 0; n2 < NCIT; n2++) acc += g_Lc[m*NCIT + n2] * xb[n2*DIN + ch];
    g_Lxc[i] = acc;
}

__global__ void k_init_y(const float* __restrict__ xh_s, const float* __restrict__ xh_c) {
    int i = blockIdx.x * blockDim.x + threadIdx.x;
    if (i < NB*NSTA) {
        int b = i / NSTA, n = i % NSTA;
        g_ys[i] = xh_s[(b*TH + (TH-1))*NSTA + n];
    } else if (i < NB*NSTA + NB*NCIT) {
        int k = i - NB*NSTA;
        int b = k / NCIT, n = k % NCIT;
        g_yc[k] = xh_c[(b*TH + (TH-1))*NCIT + n];
    }
}

__global__ void k_zero_h() {
    int i = blockIdx.x * blockDim.x + threadIdx.x;
    if (i < NB*NSTA*HH) g_hs[i] = 0.f;
    else if (i < NB*NSTA*HH + NB*NCIT*HH) g_hc[i - NB*NSTA*HH] = 0.f;
}

// ---------------- pred staging: build x + SpMM(L_s) + dense L_c, fused ----------------
#define ZA_BLKS (((NB*NSTA*DIN) + (NB*NCIT*DIN) + 255) / 256)   // 3808
#define ZB_BLKS ((NSTA*NB) / 8)                                  // 4096 (8 warps/block)
#define ZC_BLKS (((NB*NCIT*DIN) + 255) / 256)                    // 224

__global__ void k_stage(const float* __restrict__ ft_s, const float* __restrict__ ft_c, int tt) {
    int bid = blockIdx.x;
    int tid = threadIdx.x;
    if (bid < ZA_BLKS) {
        int i = bid * 256 + tid;
        const int nS = NB*NSTA*DIN;
        const int nC = NB*NCIT*DIN;
        if (i < nS) {
            int ch = i % DIN; int r = i / DIN; int n = r % NSTA; int b = r / NSTA;
            g_xs[i] = (ch == 0) ? g_ys[r] : ft_s[((b*TT + tt)*NSTA + n)*DM + (ch-1)];
        } else if (i < nS + nC) {
            int k = i - nS;
            int ch = k % DIN; int r = k / DIN; int n = r % NCIT; int b = r / NCIT;
            g_xc[k] = (ch == 0) ? g_yc[r] : ft_c[((b*TT + tt)*NCIT + n)*DM + (ch-1)];
        }
    } else if (bid < ZA_BLKS + ZB_BLKS) {
        int wid = (bid - ZA_BLKS) * 8 + (tid >> 5);
        int lane = tid & 31;
        int m = wid >> 3;       // station
        int b = wid & 7;        // batch
        if (lane < DIN) {
            int beg = g_Ls_rowptr[m], end = g_Ls_rowptr[m+1];
            float acc = 0.f;
            if (lane == 0) {
                const float* yb = g_ys + b*NSTA;
                for (int p = beg; p < end; p++) acc += g_Ls_vals[p] * yb[g_Ls_cols[p]];
            } else {
                const float* fb = ft_s + ((size_t)(b*TT + tt)*NSTA)*DM + (lane-1);
                for (int p = beg; p < end; p++) acc += g_Ls_vals[p] * fb[(size_t)g_Ls_cols[p]*DM];
            }
            g_Lxs[((size_t)b*NSTA + m)*DIN + lane] = acc;
        }
    } else {
        int i = (bid - ZA_BLKS - ZB_BLKS) * 256 + tid;
        if (i < NB*NCIT*DIN) {
            int ch = i % DIN; int r = i / DIN; int m = r % NCIT; int b = r / NCIT;
            float acc = 0.f;
            if (ch == 0) {
                const float* yb = g_yc + b*NCIT;
                for (int n2 = 0; n2 < NCIT; n2++) acc += g_Lc[m*NCIT + n2] * yb[n2];
            } else {
                const float* fb = ft_c + ((size_t)(b*TT + tt)*NCIT)*DM + (ch-1);
                for (int n2 = 0; n2 < NCIT; n2++) acc += g_Lc[m*NCIT + n2] * fb[(size_t)n2*DM];
            }
            g_Lxc[i] = acc;
        }
    }
}

// ---------------- Cheb conv v2: out = sigmoid([x|Lx] @ W + b), tiled 64x64 ----------------
// 256 threads: tx = tid&31 owns cols {2tx, 2tx+1}; ty = tid>>5 owns rows ty*8..ty*8+7
__global__ __launch_bounds__(256) void k_cheb2(
        const float* __restrict__ xS, const float* __restrict__ lxS,
        const float* __restrict__ wS, const float* __restrict__ bS,
        float* __restrict__ outS, int ntS,
        const float* __restrict__ xC, const float* __restrict__ lxC,
        const float* __restrict__ wC, const float* __restrict__ bC,
        float* __restrict__ outC, int ntC, int nbS) {
    extern __shared__ float sm[];
    float* sw = sm;               // 56*64
    float* sx = sw + 56*64;       // 56*64
    float* sb = sx + 56*64;       // 64
    const float *x, *lx, *w, *bias; float* out; int nt, t0, tstep;
    if ((int)blockIdx.x < nbS) { x=xS; lx=lxS; w=wS; bias=bS; out=outS; nt=ntS; t0=blockIdx.x; tstep=nbS; }
    else { x=xC; lx=lxC; w=wC; bias=bC; out=outC; nt=ntC; t0=blockIdx.x-nbS; tstep=gridDim.x-nbS; }
    int tid = threadIdx.x, tx = tid & 31, ty = tid >> 5;
    for (int i = tid; i < 56*64; i += 256) sw[i] = w[i];
    if (tid < 64) sb[tid] = bias[tid];
    __syncthreads();
    for (int tile = t0; tile < nt; tile += tstep) {
        long r0 = (long)tile << 6;
        for (int i = tid; i < 56*64; i += 256) {
            int rr = i & 63, ch = i >> 6;
            float v = (ch < DIN) ? x[(r0+rr)*DIN + ch] : lx[(r0+rr)*DIN + (ch-DIN)];
            sx[ch*64 + rr] = v;
        }
        __syncthreads();
        ull a0[4] = {0,0,0,0}, a1[4] = {0,0,0,0};
        int xoff = ty * 8;
        #pragma unroll 2
        for (int ch = 0; ch < 56; ch++) {
            const float* xr = &sx[ch*64 + xoff];
            ulonglong2 xv0 = *(const ulonglong2*)(xr);
            ulonglong2 xv1 = *(const ulonglong2*)(xr + 4);
            float2 wv = *(const float2*)&sw[ch*64 + 2*tx];
            ull w0 = splat2(wv.x), w1 = splat2(wv.y);
            fma2(a0[0], xv0.x, w0); fma2(a0[1], xv0.y, w0);
            fma2(a0[2], xv1.x, w0); fma2(a0[3], xv1.y, w0);
            fma2(a1[0], xv0.x, w1); fma2(a1[1], xv0.y, w1);
            fma2(a1[2], xv1.x, w1); fma2(a1[3], xv1.y, w1);
        }
        float b0 = sb[2*tx], b1 = sb[2*tx+1];
        #pragma unroll
        for (int rk = 0; rk < 4; rk++) {
            float2 v0 = unp2(a0[rk]);
            float2 v1 = unp2(a1[rk]);
            long r = r0 + xoff + rk*2;
            out[r*64 + 2*tx]       = sigm(v0.x + b0);
            out[r*64 + 2*tx + 1]   = sigm(v1.x + b1);
            out[(r+1)*64 + 2*tx]   = sigm(v0.y + b0);
            out[(r+1)*64 + 2*tx+1] = sigm(v1.y + b1);
        }
        __syncthreads();
    }
}

// ---------------- fuse v2: fx = xg + (A_gather(xg_other)) @ W + b ----------------
__global__ __launch_bounds__(256) void k_fuse2(
        const float* __restrict__ xgS, const float* __restrict__ xgC,
        const float* __restrict__ wS, const float* __restrict__ bS, float* __restrict__ fxS, int ntS,
        const float* __restrict__ wC, const float* __restrict__ bC, float* __restrict__ fxC, int ntC,
        int nbS) {
    extern __shared__ float sm[];
    float* sw   = sm;             // 64*64
    float* sb   = sw + 64*64;     // 64
    float* stmp = sb + 64;        // 64*68 (pad 4)
    bool isC = (int)blockIdx.x >= nbS;
    const float* xg    = isC ? xgC : xgS;
    const float* other = isC ? xgS : xgC;
    const float* w     = isC ? wC  : wS;
    const float* bias  = isC ? bC  : bS;
    float* fx          = isC ? fxC : fxS;
    int nt = isC ? ntC : ntS;
    int t0 = isC ? (blockIdx.x - nbS) : blockIdx.x;
    int tstep = isC ? (gridDim.x - nbS) : nbS;
    const int* rowptr = isC ? g_afcT_rowptr : g_afc_rowptr;
    const int* colsA  = isC ? g_afcT_cols   : g_afc_cols;
    int shN   = isC ? 8 : 12;           // log2(Nnode)
    int otherStride = isC ? (NSTA*GF) : (NCIT*GF);
    int tid = threadIdx.x, tx = tid & 31, ty = tid >> 5;
    for (int i = tid; i < 64*64; i += 256) sw[i] = w[i];
    if (tid < 64) sb[tid] = bias[tid];
    __syncthreads();
    for (int tile = t0; tile < nt; tile += tstep) {
        long r0 = (long)tile << 6;
        // gather
        for (int i = tid; i < 64*64; i += 256) {
            int row = i >> 6, ch = i & 63;
            long rg = r0 + row;
            int tb = (int)(rg >> shN);
            int node = (int)(rg & ((1 << shN) - 1));
            int beg = rowptr[node], end = rowptr[node+1];
            const float* src = other + (size_t)tb * otherStride;
            float acc = 0.f;
            for (int p = beg; p < end; p++) acc += src[colsA[p]*GF + ch];
            stmp[ch*68 + row] = acc;
        }
        __syncthreads();
        ull a0[4] = {0,0,0,0}, a1[4] = {0,0,0,0};
        int xoff = ty * 8;
        #pragma unroll 2
        for (int ch = 0; ch < 64; ch++) {
            const float* xr = &stmp[ch*68 + xoff];
            ulonglong2 xv0 = *(const ulonglong2*)(xr);
            ulonglong2 xv1 = *(const ulonglong2*)(xr + 4);
            float2 wv = *(const float2*)&sw[ch*64 + 2*tx];
            ull w0 = splat2(wv.x), w1 = splat2(wv.y);
            fma2(a0[0], xv0.x, w0); fma2(a0[1], xv0.y, w0);
            fma2(a0[2], xv1.x, w0); fma2(a0[3], xv1.y, w0);
            fma2(a1[0], xv0.x, w1); fma2(a1[1], xv0.y, w1);
            fma2(a1[2], xv1.x, w1); fma2(a1[3], xv1.y, w1);
        }
        float b0 = sb[2*tx], b1 = sb[2*tx+1];
        #pragma unroll
        for (int rk = 0; rk < 4; rk++) {
            float2 v0 = unp2(a0[rk]);
            float2 v1 = unp2(a1[rk]);
            long r = r0 + xoff + rk*2;
            fx[r*64 + 2*tx]       = xg[r*64 + 2*tx]       + v0.x + b0;
            fx[r*64 + 2*tx + 1]   = xg[r*64 + 2*tx + 1]   + v1.x + b1;
            fx[(r+1)*64 + 2*tx]   = xg[(r+1)*64 + 2*tx]   + v0.y + b0;
            fx[(r+1)*64 + 2*tx+1] = xg[(r+1)*64 + 2*tx+1] + v1.y + b1;
        }
        __syncthreads();
    }
}

// ---------------- GRU v2: persistent smem weights, 64x192 tile, f32x2 ----------------
struct GruP {
    const float *xa, *xg; float* h;
    const float *wi, *wh, *bi, *bh;
    const float *fcw, *fcb; float *ybuf, *yout;
    int nrows, nnodes;
};

#define GRU_SMEM_FLOATS (DGRU*NG + HH*NG + 156*64 + NG + NG)

__global__ __launch_bounds__(256, 1) void k_gru2(GruP ps, GruP pc, int idx, int step) {
    extern __shared__ float sm[];
    float* swi = sm;                         // 92*192
    float* swh = swi + DGRU*NG;              // 64*192
    float* sxh = swh + HH*NG;                // 156*64
    float* sbi = sxh + 156*64;               // 192
    float* sbh = sbi + NG;                   // 192

    bool isC = (int)blockIdx.x >= NBLK_S;
    GruP P = isC ? pc : ps;
    int nt = P.nrows >> 6;
    int t0 = isC ? ((int)blockIdx.x - NBLK_S) : (int)blockIdx.x;
    int tstep = isC ? NBLK_C : NBLK_S;

    int tid = threadIdx.x, tx = tid & 31, ty = tid >> 5;
    for (int i = tid; i < DGRU*NG; i += 256) swi[i] = P.wi[i];
    for (int i = tid; i < HH*NG; i += 256) swh[i] = P.wh[i];
    if (tid < NG) { sbi[tid] = P.bi[tid]; sbh[tid] = P.bh[tid]; }
    __syncthreads();

    const int xoff = ty * 8;
    for (int tile = t0; tile < nt; tile += tstep) {
        long r0 = (long)tile << 6;
        for (int i = tid; i < 156*64; i += 256) {
            int rr = i & 63, ch = i >> 6;
            long r = r0 + rr;
            float v;
            if (ch < DIN) v = P.xa[r*DIN + ch];
            else if (ch < DGRU) v = P.xg[r*GF + (ch - DIN)];
            else v = P.h[r*HH + (ch - DGRU)];
            sxh[ch*64 + rr] = v;
        }
        __syncthreads();

        ull ai2[6][4];
        ull ah2[6][4];
        #pragma unroll
        for (int m = 0; m < 6; m++)
            #pragma unroll
            for (int k = 0; k < 4; k++) { ai2[m][k] = 0ull; ah2[m][k] = 0ull; }

        #pragma unroll 2
        for (int ch = 0; ch < DGRU; ch++) {
            const float* xr = &sxh[ch*64 + xoff];
            ulonglong2 xv0 = *(const ulonglong2*)(xr);
            ulonglong2 xv1 = *(const ulonglong2*)(xr + 4);
            const float* wr = &swi[ch*NG + tx];
            #pragma unroll
            for (int m = 0; m < 6; m++) {
                ull w2 = splat2(wr[32*m]);
                fma2(ai2[m][0], xv0.x, w2); fma2(ai2[m][1], xv0.y, w2);
                fma2(ai2[m][2], xv1.x, w2); fma2(ai2[m][3], xv1.y, w2);
            }
        }
        #pragma unroll 2
        for (int ch = 0; ch < HH; ch++) {
            const float* xr = &sxh[(DGRU+ch)*64 + xoff];
            ulonglong2 xv0 = *(const ulonglong2*)(xr);
            ulonglong2 xv1 = *(const ulonglong2*)(xr + 4);
            const float* wr = &swh[ch*NG + tx];
            #pragma unroll
            for (int m = 0; m < 6; m++) {
                ull w2 = splat2(wr[32*m]);
                fma2(ah2[m][0], xv0.x, w2); fma2(ah2[m][1], xv0.y, w2);
                fma2(ah2[m][2], xv1.x, w2); fma2(ah2[m][3], xv1.y, w2);
            }
        }

        float part[8];
        #pragma unroll
        for (int u = 0; u < 8; u++) part[u] = 0.f;

        #pragma unroll
        for (int hh = 0; hh < 2; hh++) {
            int j = tx + (hh << 5);
            float biR = sbi[j],       bhR = sbh[j];
            float biZ = sbi[j + 64],  bhZ = sbh[j + 64];
            float biN = sbi[j + 128], bhN = sbh[j + 128];
            int iv = 1 << (j >> 4);
            bool upd = (idx & (iv - 1)) == 0;
            float fw = P.yout ? P.fcw[j] : 0.f;
            #pragma unroll
            for (int rk = 0; rk < 4; rk++) {
                float2 aR = unp2(ai2[hh][rk]),     hR = unp2(ah2[hh][rk]);
                float2 aZ = unp2(ai2[2+hh][rk]),   hZ = unp2(ah2[2+hh][rk]);
                float2 aN = unp2(ai2[4+hh][rk]),   hN = unp2(ah2[4+hh][rk]);
                #pragma unroll
                for (int u = 0; u < 2; u++) {
                    int rr = xoff + rk*2 + u;
                    long r = r0 + rr;
                    float avR = u ? aR.y : aR.x, hvR = u ? hR.y : hR.x;
                    float avZ = u ? aZ.y : aZ.x, hvZ = u ? hZ.y : hZ.x;
                    float avN = u ? aN.y : aN.x, hvN = u ? hN.y : hN.x;
                    float hold = sxh[(DGRU+j)*64 + rr];
                    float rg = sigm(avR + biR + hvR + bhR);
                    float z  = sigm(avZ + biZ + hvZ + bhZ);
                    float nn = tanhf(avN + biN + rg*(hvN + bhN));
                    float hf = upd ? ((1.f - z)*nn + z*hold) : hold;
                    P.h[r*HH + j] = hf;
                    part[rk*2 + u] += hf * fw;
                }
            }
        }
        if (P.yout) {
            #pragma unroll
            for (int r8 = 0; r8 < 8; r8++) {
                float v = part[r8];
                v += __shfl_xor_sync(0xffffffffu, v, 16);
                v += __shfl_xor_sync(0xffffffffu, v, 8);
                v += __shfl_xor_sync(0xffffffffu, v, 4);
                v += __shfl_xor_sync(0xffffffffu, v, 2);
                v += __shfl_xor_sync(0xffffffffu, v, 1);
                if (tx == 0) {
                    long r = r0 + xoff + r8;
                    float y = v + P.fcb[0];
                    P.ybuf[r] = y;
                    int b = (int)(r / P.nnodes), n = (int)(r % P.nnodes);
                    P.yout[((size_t)b*TP + step)*P.nnodes + n] = y;
                }
            }
        }
        __syncthreads();
    }
}

// ---------------- host ----------------
static void* symaddr(const void* sym) {
    void* p = nullptr;
    cudaGetSymbolAddress(&p, sym);
    return p;
}

extern "C" void kernel_launch(void* const* d_in, const int* in_sizes, int n_in,
                              void* d_out, int out_size) {
    const float* x_hist     = (const float*)d_in[0];
    const float* features   = (const float*)d_in[1];
    const float* c_x_hist   = (const float*)d_in[2];
    const float* c_features = (const float*)d_in[3];
    const float* adj_sta    = (const float*)d_in[4];
    const float* adj_city   = (const float*)d_in[5];
    const float* afc        = (const float*)d_in[6];
    const float* conv_w     = (const float*)d_in[7];
    const float* conv_b     = (const float*)d_in[8];
    const float* c_conv_w   = (const float*)d_in[9];
    const float* c_conv_b   = (const float*)d_in[10];
    const float* gru_wi     = (const float*)d_in[11];
    const float* gru_wh     = (const float*)d_in[12];
    const float* gru_bi     = (const float*)d_in[13];
    const float* gru_bh     = (const float*)d_in[14];
    const float* c_gru_wi   = (const float*)d_in[15];
    const float* c_gru_wh   = (const float*)d_in[16];
    const float* c_gru_bi   = (const float*)d_in[17];
    const float* c_gru_bh   = (const float*)d_in[18];
    const float* fc_w       = (const float*)d_in[19];
    const float* fc_b       = (const float*)d_in[20];
    const float* c_fc_w     = (const float*)d_in[21];
    const float* c_fc_b     = (const float*)d_in[22];
    const float* c2s_w      = (const float*)d_in[23];
    const float* c2s_b      = (const float*)d_in[24];
    const float* s2c_w      = (const float*)d_in[25];
    const float* s2c_b      = (const float*)d_in[26];

    float* out_s = (float*)d_out;
    float* out_c = out_s + (size_t)NB * TP * NSTA;

    float* p_dinv_s     = (float*)symaddr(g_dinv_s);
    int*   p_cnt_s      = (int*)  symaddr(g_cnt_s);
    int*   p_Ls_rowptr  = (int*)  symaddr(g_Ls_rowptr);
    int*   p_Ls_cols    = (int*)  symaddr(g_Ls_cols);
    float* p_Ls_vals    = (float*)symaddr(g_Ls_vals);
    int*   p_cnt_afc    = (int*)  symaddr(g_cnt_afc);
    int*   p_afc_rowptr = (int*)  symaddr(g_afc_rowptr);
    int*   p_afc_cols   = (int*)  symaddr(g_afc_cols);
    int*   p_cnt_afcT   = (int*)  symaddr(g_cnt_afcT);
    int*   p_afcT_rowptr= (int*)  symaddr(g_afcT_rowptr);
    int*   p_afcT_cols  = (int*)  symaddr(g_afcT_cols);
    int*   p_cnt_c      = (int*)  symaddr(g_cnt_c);
    float* p_dinv_c     = (float*)symaddr(g_dinv_c);
    float* p_xs   = (float*)symaddr(g_xs);
    float* p_Lxs  = (float*)symaddr(g_Lxs);
    float* p_xgs  = (float*)symaddr(g_xgs);
    float* p_fxs  = (float*)symaddr(g_fxs);
    float* p_xc   = (float*)symaddr(g_xc);
    float* p_Lxc  = (float*)symaddr(g_Lxc);
    float* p_xgc  = (float*)symaddr(g_xgc);
    float* p_fxc  = (float*)symaddr(g_fxc);
    float* p_hs   = (float*)symaddr(g_hs);
    float* p_hc   = (float*)symaddr(g_hc);
    float* p_ys   = (float*)symaddr(g_ys);
    float* p_yc   = (float*)symaddr(g_yc);

    (void)in_sizes; (void)n_in; (void)out_size;

    const int gru_smem = GRU_SMEM_FLOATS * (int)sizeof(float);
    cudaFuncSetAttribute(k_gru2, cudaFuncAttributeMaxDynamicSharedMemorySize, gru_smem);
    const int cheb_smem = (56*64 + 56*64 + 64) * (int)sizeof(float);
    const int fuse_smem = (64*64 + 64 + 64*68) * (int)sizeof(float);

    // ---- preprocessing ----
    k_count_rows<<<NSTA, 128>>>(adj_sta, p_cnt_s, p_dinv_s, NSTA, NSTA, 1);
    k_scan<<<1, 1024>>>(p_cnt_s, p_Ls_rowptr, NSTA);
    k_fill_csr<<<(NSTA+3)/4, 128>>>(adj_sta, p_Ls_rowptr, p_Ls_cols, p_Ls_vals, p_dinv_s, NSTA, NSTA, 1);

    k_count_rows<<<NSTA, 128>>>(afc, p_cnt_afc, nullptr, NSTA, NCIT, 0);
    k_scan<<<1, 1024>>>(p_cnt_afc, p_afc_rowptr, NSTA);
    k_fill_csr<<<(NSTA+3)/4, 128>>>(afc, p_afc_rowptr, p_afc_cols, nullptr, nullptr, NSTA, NCIT, 0);

    k_count_cols<<<NCIT, 128>>>(afc, p_cnt_afcT, NSTA, NCIT);
    k_scan<<<1, 1024>>>(p_cnt_afcT, p_afcT_rowptr, NCIT);
    k_fill_csrT<<<(NCIT+3)/4, 128>>>(afc, p_afcT_rowptr, p_afcT_cols, NSTA, NCIT);

    k_count_rows<<<NCIT, 128>>>(adj_city, p_cnt_c, p_dinv_c, NCIT, NCIT, 1);
    k_fill_Lc<<<NCIT, NCIT>>>(adj_city);

    // ---- history (batched over 7 steps) ----
    {
        int tot = THIST*NB*NSTA*DIN + THIST*NB*NCIT*DIN;
        k_build_hist_x<<<(tot+255)/256, 256>>>(x_hist, features, c_x_hist, c_features);
    }
    k_spmm_hist<<<(NSTA*THIST*NB + 3)/4, 128>>>(THIST*NB);
    k_lmm_hist<<<(THIST*NB*NCIT*DIN + 255)/256, 256>>>(THIST*NB);
    {
        int ntS = (THIST*NB*NSTA) / 64, ntC = (THIST*NB*NCIT) / 64;
        k_cheb2<<<ntS + ntC, 256, cheb_smem>>>(p_xs, p_Lxs, conv_w, conv_b, p_xgs, ntS,
                                               p_xc, p_Lxc, c_conv_w, c_conv_b, p_xgc, ntC, ntS);
        k_fuse2<<<ntS + ntC, 256, fuse_smem>>>(p_xgs, p_xgc, c2s_w, c2s_b, p_fxs, ntS,
                                               s2c_w, s2c_b, p_fxc, ntC, ntS);
    }
    {
        int tot = NB*NSTA*HH + NB*NCIT*HH;
        k_zero_h<<<(tot+255)/256, 256>>>();
    }
    for (int t = 0; t < THIST; t++) {
        GruP ps = { p_xs + (size_t)t*NB*NSTA*DIN, p_fxs + (size_t)t*NB*NSTA*GF, p_hs,
                    gru_wi, gru_wh, gru_bi, gru_bh,
                    nullptr, nullptr, nullptr, nullptr, NB*NSTA, NSTA };
        GruP pc = { p_xc + (size_t)t*NB*NCIT*DIN, p_fxc + (size_t)t*NB*NCIT*GF, p_hc,
                    c_gru_wi, c_gru_wh, c_gru_bi, c_gru_bh,
                    nullptr, nullptr, nullptr, nullptr, NB*NCIT, NCIT };
        k_gru2<<<GRU_GRID, 256, gru_smem>>>(ps, pc, 1 + t, 0);
    }
    {
        int tot = NB*NSTA + NB*NCIT;
        k_init_y<<<(tot+255)/256, 256>>>(x_hist, c_x_hist);
    }

    // ---- autoregressive prediction (24 steps) ----
    const int ntS = (NB*NSTA) / 64;   // 512
    const int ntC = (NB*NCIT) / 64;   // 32
    for (int s = 0; s < TP; s++) {
        int tt = TH + s;
        int idx = TH + s;
        k_stage<<<ZA_BLKS + ZB_BLKS + ZC_BLKS, 256>>>(features, c_features, tt);
        k_cheb2<<<ntS + ntC, 256, cheb_smem>>>(p_xs, p_Lxs, conv_w, conv_b, p_xgs, ntS,
                                               p_xc, p_Lxc, c_conv_w, c_conv_b, p_xgc, ntC, ntS);
        k_fuse2<<<ntS + ntC, 256, fuse_smem>>>(p_xgs, p_xgc, c2s_w, c2s_b, p_fxs, ntS,
                                               s2c_w, s2c_b, p_fxc, ntC, ntS);
        GruP ps = { p_xs, p_fxs, p_hs, gru_wi, gru_wh, gru_bi, gru_bh,
                    fc_w, fc_b, p_ys, out_s, NB*NSTA, NSTA };
        GruP pc = { p_xc, p_fxc, p_hc, c_gru_wi, c_gru_wh, c_gru_bi, c_gru_bh,
                    c_fc_w, c_fc_b, p_yc, out_c, NB*NCIT, NCIT };
        k_gru2<<<GRU_GRID, 256, gru_smem>>>(ps, pc, idx, s);
    }
}

// round 3
// speedup vs baseline: 1.2903x; 1.0320x over previous
#include <cuda_runtime.h>
#include <math.h>

#define NSTA 4096
#define NCIT 256
#define NB 8
#define TH 8
#define TP 24
#define TT 32
#define DIN 28
#define DM 27
#define GF 64
#define HH 64
#define NG 192
#define DGRU 92
#define THIST 7
#define NNZMAX (1<<20)

#define NBLK   148
#define NBLK_S 128
#define NBLK_C 20

typedef unsigned long long ull;

// ---------------- static device scratch ----------------
__device__ float g_dinv_s[NSTA];
__device__ int   g_cnt_s[NSTA];
__device__ int   g_Ls_rowptr[NSTA+1];
__device__ int   g_Ls_cols[NNZMAX];
__device__ float g_Ls_vals[NNZMAX];

__device__ int   g_cnt_afc[NSTA];
__device__ int   g_afc_rowptr[NSTA+1];
__device__ int   g_afc_cols[NNZMAX];

__device__ int   g_cnt_afcT[NCIT];
__device__ int   g_afcT_rowptr[NCIT+1];
__device__ int   g_afcT_cols[NNZMAX];

__device__ float g_dinv_c[NCIT];
__device__ int   g_cnt_c[NCIT];
__device__ float g_Lc[NCIT*NCIT];

__device__ float g_xs [THIST*NB*NSTA*DIN];
__device__ float g_Lxs[THIST*NB*NSTA*DIN];
__device__ float g_xgs[THIST*NB*NSTA*GF];
__device__ float g_fxs[THIST*NB*NSTA*GF];

__device__ float g_xc [THIST*NB*NCIT*DIN];
__device__ float g_Lxc[THIST*NB*NCIT*DIN];
__device__ float g_xgc[THIST*NB*NCIT*GF];
__device__ float g_fxc[THIST*NB*NCIT*GF];

__device__ float g_zs[NB*NSTA*GF];
__device__ float g_zc[NB*NCIT*GF];

__device__ float g_hs[NB*NSTA*HH];
__device__ float g_hc[NB*NCIT*HH];
__device__ float g_ys[NB*NSTA];
__device__ float g_yc[NB*NCIT];

// grid barrier state
__device__ unsigned g_bar_cnt = 0;
__device__ volatile unsigned g_bar_gen = 0;

// ---------------- f32x2 helpers ----------------
__device__ __forceinline__ ull splat2(float w) {
    ull r;
    asm("mov.b64 %0, {%1, %1};" : "=l"(r) : "f"(w));
    return r;
}
__device__ __forceinline__ void fma2(ull& a, ull x, ull w) {
    asm("fma.rn.f32x2 %0, %1, %2, %0;" : "+l"(a) : "l"(x), "l"(w));
}
__device__ __forceinline__ float2 unp2(ull v) {
    float2 f;
    asm("mov.b64 {%0, %1}, %2;" : "=f"(f.x), "=f"(f.y) : "l"(v));
    return f;
}
__device__ __forceinline__ float sigm(float x) { return 1.f / (1.f + __expf(-x)); }

__device__ __forceinline__ void gbar() {
    __syncthreads();
    if (threadIdx.x == 0) {
        unsigned gen = g_bar_gen;
        __threadfence();
        unsigned t = atomicAdd(&g_bar_cnt, 1);
        if (t == (unsigned)(NBLK - 1)) {
            g_bar_cnt = 0;
            __threadfence();
            g_bar_gen = gen + 1;
        } else {
            while (g_bar_gen == gen) { __nanosleep(64); }
        }
    }
    __syncthreads();
    __threadfence();
}

// ---------------- preprocessing kernels ----------------
__global__ void k_count_rows(const float* __restrict__ mat, int* __restrict__ cnt,
                             float* __restrict__ dinv, int nrows, int ncols, int excl) {
    int m = blockIdx.x;
    if (m >= nrows) return;
    int c = 0;
    for (int j = threadIdx.x; j < ncols; j += blockDim.x) {
        float v = mat[(size_t)m*ncols + j];
        if (v != 0.f && !(excl && j == m)) c++;
    }
    __shared__ int sred[128];
    sred[threadIdx.x] = c; __syncthreads();
    for (int s = 64; s > 0; s >>= 1) {
        if (threadIdx.x < s) sred[threadIdx.x] += sred[threadIdx.x + s];
        __syncthreads();
    }
    if (threadIdx.x == 0) {
        cnt[m] = sred[0];
        if (dinv) dinv[m] = (sred[0] > 0) ? rsqrtf((float)sred[0]) : 0.f;
    }
}

__global__ void k_count_cols(const float* __restrict__ mat, int* __restrict__ cnt,
                             int nrows, int ncols) {
    int c = blockIdx.x;
    if (c >= ncols) return;
    int acc = 0;
    for (int s = threadIdx.x; s < nrows; s += blockDim.x)
        if (mat[(size_t)s*ncols + c] != 0.f) acc++;
    __shared__ int sred[128];
    sred[threadIdx.x] = acc; __syncthreads();
    for (int s = 64; s > 0; s >>= 1) {
        if (threadIdx.x < s) sred[threadIdx.x] += sred[threadIdx.x + s];
        __syncthreads();
    }
    if (threadIdx.x == 0) cnt[c] = sred[0];
}

__global__ void k_scan(const int* __restrict__ cnt, int* __restrict__ rowptr, int n) {
    __shared__ int s[1024];
    int tid = threadIdx.x;
    int per = (n + 1023) / 1024;
    int base = tid * per;
    int loc = 0;
    for (int i = 0; i < per; i++) if (base + i < n) loc += cnt[base + i];
    s[tid] = loc; __syncthreads();
    for (int off = 1; off < 1024; off <<= 1) {
        int v = (tid >= off) ? s[tid - off] : 0;
        __syncthreads();
        s[tid] += v;
        __syncthreads();
    }
    int a = (tid == 0) ? 0 : s[tid - 1];
    for (int i = 0; i < per; i++) {
        if (base + i < n) { rowptr[base + i] = a; a += cnt[base + i]; }
    }
    if (tid == 1023) rowptr[n] = a;
}

__global__ void k_fill_csr(const float* __restrict__ mat, const int* __restrict__ rowptr,
                           int* __restrict__ cols, float* __restrict__ vals,
                           const float* __restrict__ dinv,
                           int nrows, int ncols, int excl) {
    int m = blockIdx.x * (blockDim.x / 32) + (threadIdx.x / 32);
    if (m >= nrows) return;
    int lane = threadIdx.x & 31;
    int pos = rowptr[m];
    float dm = dinv ? dinv[m] : 0.f;
    for (int base = 0; base < ncols; base += 32) {
        int j = base + lane;
        bool p = (j < ncols) && (mat[(size_t)m*ncols + j] != 0.f) && !(excl && j == m);
        unsigned msk = __ballot_sync(0xffffffffu, p);
        if (p) {
            int off = __popc(msk & ((1u << lane) - 1u));
            cols[pos + off] = j;
            if (vals) vals[pos + off] = -dm * dinv[j];
        }
        pos += __popc(msk);
    }
}

__global__ void k_fill_csrT(const float* __restrict__ mat, const int* __restrict__ rowptr,
                            int* __restrict__ cols, int nrows, int ncols) {
    int c = blockIdx.x * (blockDim.x / 32) + (threadIdx.x / 32);
    if (c >= ncols) return;
    int lane = threadIdx.x & 31;
    int pos = rowptr[c];
    for (int base = 0; base < nrows; base += 32) {
        int s = base + lane;
        bool p = (s < nrows) && (mat[(size_t)s*ncols + c] != 0.f);
        unsigned msk = __ballot_sync(0xffffffffu, p);
        if (p) cols[pos + __popc(msk & ((1u << lane) - 1u))] = s;
        pos += __popc(msk);
    }
}

__global__ void k_fill_Lc(const float* __restrict__ adj) {
    int m = blockIdx.x, n = threadIdx.x;
    float v = 0.f;
    if (n != m && adj[m*NCIT + n] != 0.f) v = -g_dinv_c[m] * g_dinv_c[n];
    g_Lc[m*NCIT + n] = v;
}

// ---------------- history staging ----------------
__global__ void k_build_hist_x(const float* __restrict__ xh_s, const float* __restrict__ ft_s,
                               const float* __restrict__ xh_c, const float* __restrict__ ft_c) {
    int i = blockIdx.x * blockDim.x + threadIdx.x;
    const int nS = THIST*NB*NSTA*DIN;
    const int nC = THIST*NB*NCIT*DIN;
    if (i < nS) {
        int ch = i % DIN; int r = i / DIN; int n = r % NSTA; int tb = r / NSTA;
        int b = tb % NB; int t = tb / NB;
        float v;
        if (ch == 0) v = xh_s[(b*TH + t)*NSTA + n];
        else v = ft_s[((b*TT + (t+1))*NSTA + n)*DM + (ch-1)];
        g_xs[i] = v;
    } else if (i < nS + nC) {
        int k = i - nS;
        int ch = k % DIN; int r = k / DIN; int n = r % NCIT; int tb = r / NCIT;
        int b = tb % NB; int t = tb / NB;
        float v;
        if (ch == 0) v = xh_c[(b*TH + t)*NCIT + n];
        else v = ft_c[((b*TT + (t+1))*NCIT + n)*DM + (ch-1)];
        g_xc[k] = v;
    }
}

__global__ void k_spmm_hist(int ntb) {
    int wid = blockIdx.x * 4 + (threadIdx.x >> 5);
    int lane = threadIdx.x & 31;
    if (wid >= NSTA * ntb) return;
    int m = wid / ntb;
    int tb = wid % ntb;
    int beg = g_Ls_rowptr[m], end = g_Ls_rowptr[m+1];
    const float* xb = g_xs + (size_t)tb * NSTA * DIN;
    if (lane < DIN) {
        float acc = 0.f;
        for (int p = beg; p < end; p++)
            acc += g_Ls_vals[p] * xb[g_Ls_cols[p]*DIN + lane];
        g_Lxs[((size_t)tb*NSTA + m)*DIN + lane] = acc;
    }
}

__global__ void k_lmm_hist(int ntb) {
    int i = blockIdx.x * blockDim.x + threadIdx.x;
    int total = ntb * NCIT * DIN;
    if (i >= total) return;
    int ch = i % DIN; int r = i / DIN; int m = r % NCIT; int tb = r / NCIT;
    const float* xb = g_xc + (size_t)tb * NCIT * DIN;
    float acc = 0.f;
    for (int n2 = 0; n2 < NCIT; n2++) acc += g_Lc[m*NCIT + n2] * xb[n2*DIN + ch];
    g_Lxc[i] = acc;
}

// ---------------- Cheb conv (history, standalone) ----------------
__global__ __launch_bounds__(256) void k_cheb2(
        const float* __restrict__ xS, const float* __restrict__ lxS,
        const float* __restrict__ wS, const float* __restrict__ bS,
        float* __restrict__ outS, int ntS,
        const float* __restrict__ xC, const float* __restrict__ lxC,
        const float* __restrict__ wC, const float* __restrict__ bC,
        float* __restrict__ outC, int ntC, int nbS) {
    extern __shared__ float sm[];
    float* sw = sm;
    float* sx = sw + 56*64;
    float* sb = sx + 56*64;
    const float *x, *lx, *w, *bias; float* out; int nt, t0, tstep;
    if ((int)blockIdx.x < nbS) { x=xS; lx=lxS; w=wS; bias=bS; out=outS; nt=ntS; t0=blockIdx.x; tstep=nbS; }
    else { x=xC; lx=lxC; w=wC; bias=bC; out=outC; nt=ntC; t0=blockIdx.x-nbS; tstep=gridDim.x-nbS; }
    int tid = threadIdx.x, tx = tid & 31, ty = tid >> 5;
    for (int i = tid; i < 56*64; i += 256) sw[i] = w[i];
    if (tid < 64) sb[tid] = bias[tid];
    __syncthreads();
    for (int tile = t0; tile < nt; tile += tstep) {
        long r0 = (long)tile << 6;
        for (int i = tid; i < 56*64; i += 256) {
            int rr = i & 63, ch = i >> 6;
            float v = (ch < DIN) ? x[(r0+rr)*DIN + ch] : lx[(r0+rr)*DIN + (ch-DIN)];
            sx[ch*64 + rr] = v;
        }
        __syncthreads();
        ull a0[4] = {0,0,0,0}, a1[4] = {0,0,0,0};
        int xoff = ty * 8;
        #pragma unroll 2
        for (int ch = 0; ch < 56; ch++) {
            const float* xr = &sx[ch*64 + xoff];
            ulonglong2 xv0 = *(const ulonglong2*)(xr);
            ulonglong2 xv1 = *(const ulonglong2*)(xr + 4);
            float2 wv = *(const float2*)&sw[ch*64 + 2*tx];
            ull w0 = splat2(wv.x), w1 = splat2(wv.y);
            fma2(a0[0], xv0.x, w0); fma2(a0[1], xv0.y, w0);
            fma2(a0[2], xv1.x, w0); fma2(a0[3], xv1.y, w0);
            fma2(a1[0], xv0.x, w1); fma2(a1[1], xv0.y, w1);
            fma2(a1[2], xv1.x, w1); fma2(a1[3], xv1.y, w1);
        }
        float b0 = sb[2*tx], b1 = sb[2*tx+1];
        #pragma unroll
        for (int rk = 0; rk < 4; rk++) {
            float2 v0 = unp2(a0[rk]);
            float2 v1 = unp2(a1[rk]);
            long r = r0 + xoff + rk*2;
            out[r*64 + 2*tx]       = sigm(v0.x + b0);
            out[r*64 + 2*tx + 1]   = sigm(v1.x + b1);
            out[(r+1)*64 + 2*tx]   = sigm(v0.y + b0);
            out[(r+1)*64 + 2*tx+1] = sigm(v1.y + b1);
        }
        __syncthreads();
    }
}

// ---------------- fuse (history, standalone) ----------------
__global__ __launch_bounds__(256) void k_fuse2(
        const float* __restrict__ xgS, const float* __restrict__ xgC,
        const float* __restrict__ wS, const float* __restrict__ bS, float* __restrict__ fxS, int ntS,
        const float* __restrict__ wC, const float* __restrict__ bC, float* __restrict__ fxC, int ntC,
        int nbS) {
    extern __shared__ float sm[];
    float* sw   = sm;
    float* sb   = sw + 64*64;
    float* stmp = sb + 64;
    bool isC = (int)blockIdx.x >= nbS;
    const float* xg    = isC ? xgC : xgS;
    const float* other = isC ? xgS : xgC;
    const float* w     = isC ? wC  : wS;
    const float* bias  = isC ? bC  : bS;
    float* fx          = isC ? fxC : fxS;
    int nt = isC ? ntC : ntS;
    int t0 = isC ? (blockIdx.x - nbS) : blockIdx.x;
    int tstep = isC ? (gridDim.x - nbS) : nbS;
    const int* rowptr = isC ? g_afcT_rowptr : g_afc_rowptr;
    const int* colsA  = isC ? g_afcT_cols   : g_afc_cols;
    int shN   = isC ? 8 : 12;
    int otherStride = isC ? (NSTA*GF) : (NCIT*GF);
    int tid = threadIdx.x, tx = tid & 31, ty = tid >> 5;
    for (int i = tid; i < 64*64; i += 256) sw[i] = w[i];
    if (tid < 64) sb[tid] = bias[tid];
    __syncthreads();
    for (int tile = t0; tile < nt; tile += tstep) {
        long r0 = (long)tile << 6;
        for (int i = tid; i < 64*64; i += 256) {
            int row = i >> 6, ch = i & 63;
            long rg = r0 + row;
            int tb = (int)(rg >> shN);
            int node = (int)(rg & ((1 << shN) - 1));
            int beg = rowptr[node], end = rowptr[node+1];
            const float* src = other + (size_t)tb * otherStride;
            float acc = 0.f;
            for (int p = beg; p < end; p++) acc += src[colsA[p]*GF + ch];
            stmp[ch*68 + row] = acc;
        }
        __syncthreads();
        ull a0[4] = {0,0,0,0}, a1[4] = {0,0,0,0};
        int xoff = ty * 8;
        #pragma unroll 2
        for (int ch = 0; ch < 64; ch++) {
            const float* xr = &stmp[ch*68 + xoff];
            ulonglong2 xv0 = *(const ulonglong2*)(xr);
            ulonglong2 xv1 = *(const ulonglong2*)(xr + 4);
            float2 wv = *(const float2*)&sw[ch*64 + 2*tx];
            ull w0 = splat2(wv.x), w1 = splat2(wv.y);
            fma2(a0[0], xv0.x, w0); fma2(a0[1], xv0.y, w0);
            fma2(a0[2], xv1.x, w0); fma2(a0[3], xv1.y, w0);
            fma2(a1[0], xv0.x, w1); fma2(a1[1], xv0.y, w1);
            fma2(a1[2], xv1.x, w1); fma2(a1[3], xv1.y, w1);
        }
        float b0 = sb[2*tx], b1 = sb[2*tx+1];
        #pragma unroll
        for (int rk = 0; rk < 4; rk++) {
            float2 v0 = unp2(a0[rk]);
            float2 v1 = unp2(a1[rk]);
            long r = r0 + xoff + rk*2;
            fx[r*64 + 2*tx]       = xg[r*64 + 2*tx]       + v0.x + b0;
            fx[r*64 + 2*tx + 1]   = xg[r*64 + 2*tx + 1]   + v1.x + b1;
            fx[(r+1)*64 + 2*tx]   = xg[(r+1)*64 + 2*tx]   + v0.y + b0;
            fx[(r+1)*64 + 2*tx+1] = xg[(r+1)*64 + 2*tx+1] + v1.y + b1;
        }
        __syncthreads();
    }
}

// ================= MEGAKERNEL =================
struct MegaP {
    const float *features, *c_features, *x_hist, *c_x_hist;
    const float *gwi_s, *gwh_s, *gbi_s, *gbh_s;
    const float *gwi_c, *gwh_c, *gbi_c, *gbh_c;
    const float *conv_w, *conv_b, *c_conv_w, *c_conv_b;
    const float *c2s_w, *c2s_b, *s2c_w, *s2c_b;
    const float *fc_w, *fc_b, *c_fc_w, *c_fc_b;
    float *out_s, *out_c;
};

#define SCRATCH_FLOATS 10240
#define MEGA_SMEM_FLOATS (DGRU*NG + HH*NG + NG + NG + SCRATCH_FLOATS)

__device__ __noinline__ void gru_phase(
        const float* swi, const float* swh, const float* sbi, const float* sbh,
        float* sxh,
        const float* xa, const float* xg, float* h,
        int t0, int tstep, int nt, int idx,
        const float* fcw, const float* fcb, float* ybuf, float* yout,
        int nnodes, int step) {
    int tid = threadIdx.x, tx = tid & 31, ty = tid >> 5;
    const int xoff = ty * 8;
    for (int tile = t0; tile < nt; tile += tstep) {
        long r0 = (long)tile << 6;
        for (int i = tid; i < 156*64; i += 256) {
            int rr = i & 63, ch = i >> 6;
            long r = r0 + rr;
            float v;
            if (ch < DIN) v = xa[r*DIN + ch];
            else if (ch < DGRU) v = xg[r*GF + (ch - DIN)];
            else v = h[r*HH + (ch - DGRU)];
            sxh[ch*64 + rr] = v;
        }
        __syncthreads();

        ull ai2[6][4];
        ull ah2[6][4];
        #pragma unroll
        for (int m = 0; m < 6; m++)
            #pragma unroll
            for (int k = 0; k < 4; k++) { ai2[m][k] = 0ull; ah2[m][k] = 0ull; }

        #pragma unroll 2
        for (int ch = 0; ch < DGRU; ch++) {
            const float* xr = &sxh[ch*64 + xoff];
            ulonglong2 xv0 = *(const ulonglong2*)(xr);
            ulonglong2 xv1 = *(const ulonglong2*)(xr + 4);
            const float* wr = &swi[ch*NG + tx];
            #pragma unroll
            for (int m = 0; m < 6; m++) {
                ull w2 = splat2(wr[32*m]);
                fma2(ai2[m][0], xv0.x, w2); fma2(ai2[m][1], xv0.y, w2);
                fma2(ai2[m][2], xv1.x, w2); fma2(ai2[m][3], xv1.y, w2);
            }
        }
        #pragma unroll 2
        for (int ch = 0; ch < HH; ch++) {
            const float* xr = &sxh[(DGRU+ch)*64 + xoff];
            ulonglong2 xv0 = *(const ulonglong2*)(xr);
            ulonglong2 xv1 = *(const ulonglong2*)(xr + 4);
            const float* wr = &swh[ch*NG + tx];
            #pragma unroll
            for (int m = 0; m < 6; m++) {
                ull w2 = splat2(wr[32*m]);
                fma2(ah2[m][0], xv0.x, w2); fma2(ah2[m][1], xv0.y, w2);
                fma2(ah2[m][2], xv1.x, w2); fma2(ah2[m][3], xv1.y, w2);
            }
        }

        float part[8];
        #pragma unroll
        for (int u = 0; u < 8; u++) part[u] = 0.f;

        #pragma unroll
        for (int hh = 0; hh < 2; hh++) {
            int j = tx + (hh << 5);
            float biR = sbi[j],       bhR = sbh[j];
            float biZ = sbi[j + 64],  bhZ = sbh[j + 64];
            float biN = sbi[j + 128], bhN = sbh[j + 128];
            int iv = 1 << (j >> 4);
            bool upd = (idx & (iv - 1)) == 0;
            float fw = yout ? fcw[j] : 0.f;
            #pragma unroll
            for (int rk = 0; rk < 4; rk++) {
                float2 aR = unp2(ai2[hh][rk]),     hR = unp2(ah2[hh][rk]);
                float2 aZ = unp2(ai2[2+hh][rk]),   hZ = unp2(ah2[2+hh][rk]);
                float2 aN = unp2(ai2[4+hh][rk]),   hN = unp2(ah2[4+hh][rk]);
                #pragma unroll
                for (int u = 0; u < 2; u++) {
                    int rr = xoff + rk*2 + u;
                    long r = r0 + rr;
                    float avR = u ? aR.y : aR.x, hvR = u ? hR.y : hR.x;
                    float avZ = u ? aZ.y : aZ.x, hvZ = u ? hZ.y : hZ.x;
                    float avN = u ? aN.y : aN.x, hvN = u ? hN.y : hN.x;
                    float hold = sxh[(DGRU+j)*64 + rr];
                    float rg = sigm(avR + biR + hvR + bhR);
                    float z  = sigm(avZ + biZ + hvZ + bhZ);
                    float nn = tanhf(avN + biN + rg*(hvN + bhN));
                    float hf = upd ? ((1.f - z)*nn + z*hold) : hold;
                    h[r*HH + j] = hf;
                    part[rk*2 + u] += hf * fw;
                }
            }
        }
        if (yout) {
            #pragma unroll
            for (int r8 = 0; r8 < 8; r8++) {
                float v = part[r8];
                v += __shfl_xor_sync(0xffffffffu, v, 16);
                v += __shfl_xor_sync(0xffffffffu, v, 8);
                v += __shfl_xor_sync(0xffffffffu, v, 4);
                v += __shfl_xor_sync(0xffffffffu, v, 2);
                v += __shfl_xor_sync(0xffffffffu, v, 1);
                if (tx == 0) {
                    long r = r0 + xoff + r8;
                    float y = v + fcb[0];
                    ybuf[r] = y;
                    int b = (int)(r / nnodes), n = (int)(r % nnodes);
                    yout[((size_t)b*TP + step)*nnodes + n] = y;
                }
            }
        }
        __syncthreads();
    }
}

__device__ __noinline__ void cheb_phase(float* scratch,
        const float* x, const float* lx, const float* w, const float* bias,
        float* out, int t0, int tstep, int nt) {
    float* sw = scratch;
    float* sx = sw + 56*64;
    float* sb = sx + 56*64;
    int tid = threadIdx.x, tx = tid & 31, ty = tid >> 5;
    for (int i = tid; i < 56*64; i += 256) sw[i] = w[i];
    if (tid < 64) sb[tid] = bias[tid];
    __syncthreads();
    for (int tile = t0; tile < nt; tile += tstep) {
        long r0 = (long)tile << 6;
        for (int i = tid; i < 56*64; i += 256) {
            int rr = i & 63, ch = i >> 6;
            float v = (ch < DIN) ? x[(r0+rr)*DIN + ch] : lx[(r0+rr)*DIN + (ch-DIN)];
            sx[ch*64 + rr] = v;
        }
        __syncthreads();
        ull a0[4] = {0,0,0,0}, a1[4] = {0,0,0,0};
        int xoff = ty * 8;
        #pragma unroll 2
        for (int ch = 0; ch < 56; ch++) {
            const float* xr = &sx[ch*64 + xoff];
            ulonglong2 xv0 = *(const ulonglong2*)(xr);
            ulonglong2 xv1 = *(const ulonglong2*)(xr + 4);
            float2 wv = *(const float2*)&sw[ch*64 + 2*tx];
            ull w0 = splat2(wv.x), w1 = splat2(wv.y);
            fma2(a0[0], xv0.x, w0); fma2(a0[1], xv0.y, w0);
            fma2(a0[2], xv1.x, w0); fma2(a0[3], xv1.y, w0);
            fma2(a1[0], xv0.x, w1); fma2(a1[1], xv0.y, w1);
            fma2(a1[2], xv1.x, w1); fma2(a1[3], xv1.y, w1);
        }
        float b0 = sb[2*tx], b1 = sb[2*tx+1];
        #pragma unroll
        for (int rk = 0; rk < 4; rk++) {
            float2 v0 = unp2(a0[rk]);
            float2 v1 = unp2(a1[rk]);
            long r = r0 + xoff + rk*2;
            out[r*64 + 2*tx]       = sigm(v0.x + b0);
            out[r*64 + 2*tx + 1]   = sigm(v1.x + b1);
            out[(r+1)*64 + 2*tx]   = sigm(v0.y + b0);
            out[(r+1)*64 + 2*tx+1] = sigm(v1.y + b1);
        }
        __syncthreads();
    }
}

// z = xg @ W (no bias, no activation)
__device__ __noinline__ void zgemm_phase(float* scratch,
        const float* xg, const float* w, float* z, int t0, int tstep, int nt) {
    float* sw = scratch;
    float* sx = sw + 64*64;
    int tid = threadIdx.x, tx = tid & 31, ty = tid >> 5;
    for (int i = tid; i < 64*64; i += 256) sw[i] = w[i];
    __syncthreads();
    for (int tile = t0; tile < nt; tile += tstep) {
        long r0 = (long)tile << 6;
        for (int i = tid; i < 64*64; i += 256) {
            int rr = i & 63, ch = i >> 6;
            sx[ch*64 + rr] = xg[(r0+rr)*64 + ch];
        }
        __syncthreads();
        ull a0[4] = {0,0,0,0}, a1[4] = {0,0,0,0};
        int xoff = ty * 8;
        #pragma unroll 2
        for (int ch = 0; ch < 64; ch++) {
            const float* xr = &sx[ch*64 + xoff];
            ulonglong2 xv0 = *(const ulonglong2*)(xr);
            ulonglong2 xv1 = *(const ulonglong2*)(xr + 4);
            float2 wv = *(const float2*)&sw[ch*64 + 2*tx];
            ull w0 = splat2(wv.x), w1 = splat2(wv.y);
            fma2(a0[0], xv0.x, w0); fma2(a0[1], xv0.y, w0);
            fma2(a0[2], xv1.x, w0); fma2(a0[3], xv1.y, w0);
            fma2(a1[0], xv0.x, w1); fma2(a1[1], xv0.y, w1);
            fma2(a1[2], xv1.x, w1); fma2(a1[3], xv1.y, w1);
        }
        #pragma unroll
        for (int rk = 0; rk < 4; rk++) {
            float2 v0 = unp2(a0[rk]);
            float2 v1 = unp2(a1[rk]);
            long r = r0 + xoff + rk*2;
            z[r*64 + 2*tx]       = v0.x;
            z[r*64 + 2*tx + 1]   = v1.x;
            z[(r+1)*64 + 2*tx]   = v0.y;
            z[(r+1)*64 + 2*tx+1] = v1.y;
        }
        __syncthreads();
    }
}

// fx = xg + gather(z_other) + b  (float4 over channels)
__device__ __noinline__ void scatter_phase(const float* c2s_b, const float* s2c_b) {
    int g = blockIdx.x * 256 + threadIdx.x;
    const int GS = NBLK * 256;
    for (int i = g; i < NB*NSTA*16; i += GS) {
        int c4 = i & 15; int r = i >> 4;
        int node = r & (NSTA-1); int b = r >> 12;
        float4 acc = ((const float4*)c2s_b)[c4];
        int beg = g_afc_rowptr[node], end = g_afc_rowptr[node+1];
        const float4* src = (const float4*)g_zc + (size_t)b*NCIT*16;
        for (int p = beg; p < end; p++) {
            float4 v = src[g_afc_cols[p]*16 + c4];
            acc.x += v.x; acc.y += v.y; acc.z += v.z; acc.w += v.w;
        }
        float4 xv = ((const float4*)g_xgs)[i];
        acc.x += xv.x; acc.y += xv.y; acc.z += xv.z; acc.w += xv.w;
        ((float4*)g_fxs)[i] = acc;
    }
    for (int i = g; i < NB*NCIT*16; i += GS) {
        int c4 = i & 15; int r = i >> 4;
        int node = r & (NCIT-1); int b = r >> 8;
        float4 acc = ((const float4*)s2c_b)[c4];
        int beg = g_afcT_rowptr[node], end = g_afcT_rowptr[node+1];
        const float4* src = (const float4*)g_zs + (size_t)b*NSTA*16;
        for (int p = beg; p < end; p++) {
            float4 v = src[g_afcT_cols[p]*16 + c4];
            acc.x += v.x; acc.y += v.y; acc.z += v.z; acc.w += v.w;
        }
        float4 xv = ((const float4*)g_xgc)[i];
        acc.x += xv.x; acc.y += xv.y; acc.z += xv.z; acc.w += xv.w;
        ((float4*)g_fxc)[i] = acc;
    }
}

__device__ __noinline__ void stageA_phase(const float* ft_s, const float* ft_c, int tt) {
    int g = blockIdx.x * 256 + threadIdx.x;
    const int GS = NBLK * 256;
    for (int i = g; i < NB*NSTA*DIN; i += GS) {
        int ch = i % DIN; int r = i / DIN; int n = r & (NSTA-1); int b = r >> 12;
        g_xs[i] = (ch == 0) ? g_ys[r] : ft_s[((size_t)(b*TT + tt)*NSTA + n)*DM + (ch-1)];
    }
    for (int i = g; i < NB*NCIT*DIN; i += GS) {
        int ch = i % DIN; int r = i / DIN; int n = r & (NCIT-1); int b = r >> 8;
        g_xc[i] = (ch == 0) ? g_yc[r] : ft_c[((size_t)(b*TT + tt)*NCIT + n)*DM + (ch-1)];
    }
}

__device__ __noinline__ void stageB_phase() {
    int gw = (blockIdx.x * 256 + threadIdx.x) >> 5;
    int lane = threadIdx.x & 31;
    const int NW = NBLK * 8;
    for (int task = gw; task < NSTA*NB; task += NW) {
        int m = task >> 3, b = task & 7;
        if (lane < DIN) {
            int beg = g_Ls_rowptr[m], end = g_Ls_rowptr[m+1];
            const float* xb = g_xs + (size_t)b*NSTA*DIN;
            float acc = 0.f;
            for (int p = beg; p < end; p++)
                acc += g_Ls_vals[p] * xb[g_Ls_cols[p]*DIN + lane];
            g_Lxs[((size_t)b*NSTA + m)*DIN + lane] = acc;
        }
    }
    int g = blockIdx.x * 256 + threadIdx.x;
    const int GS = NBLK * 256;
    for (int i = g; i < NB*NCIT*DIN; i += GS) {
        int ch = i % DIN; int r = i / DIN; int m = r & (NCIT-1); int b = r >> 8;
        const float* xb = g_xc + (size_t)b*NCIT*DIN;
        float acc = 0.f;
        for (int n2 = 0; n2 < NCIT; n2++) acc += g_Lc[m*NCIT + n2] * xb[n2*DIN + ch];
        g_Lxc[i] = acc;
    }
}

__global__ __launch_bounds__(256, 1) void k_mega(MegaP P) {
    extern __shared__ float sm[];
    float* swi = sm;
    float* swh = swi + DGRU*NG;
    float* sbi = swh + HH*NG;
    float* sbh = sbi + NG;
    float* scratch = sbh + NG;

    int bid = blockIdx.x, tid = threadIdx.x;
    bool isC = bid >= NBLK_S;

    // persistent GRU weights
    {
        const float* wi = isC ? P.gwi_c : P.gwi_s;
        const float* wh = isC ? P.gwh_c : P.gwh_s;
        const float* bi = isC ? P.gbi_c : P.gbi_s;
        const float* bh = isC ? P.gbh_c : P.gbh_s;
        for (int i = tid; i < DGRU*NG; i += 256) swi[i] = wi[i];
        for (int i = tid; i < HH*NG; i += 256) swh[i] = wh[i];
        if (tid < NG) { sbi[tid] = bi[tid]; sbh[tid] = bh[tid]; }
    }

    // init h, ys, yc
    {
        int g = bid * 256 + tid;
        const int GS = NBLK * 256;
        for (int i = g; i < NB*NSTA*HH; i += GS) g_hs[i] = 0.f;
        for (int i = g; i < NB*NCIT*HH; i += GS) g_hc[i] = 0.f;
        for (int i = g; i < NB*NSTA; i += GS) {
            int b = i >> 12, n = i & (NSTA-1);
            g_ys[i] = P.x_hist[(b*TH + (TH-1))*NSTA + n];
        }
        for (int i = g; i < NB*NCIT; i += GS) {
            int b = i >> 8, n = i & (NCIT-1);
            g_yc[i] = P.c_x_hist[(b*TH + (TH-1))*NCIT + n];
        }
    }
    gbar();

    // ---- history GRU (7 steps) ----
    #pragma unroll 1
    for (int t = 0; t < THIST; t++) {
        if (!isC)
            gru_phase(swi, swh, sbi, sbh, scratch,
                      g_xs + (size_t)t*NB*NSTA*DIN, g_fxs + (size_t)t*NB*NSTA*GF, g_hs,
                      bid, NBLK_S, (NB*NSTA) >> 6, 1 + t,
                      nullptr, nullptr, nullptr, nullptr, NSTA, 0);
        else
            gru_phase(swi, swh, sbi, sbh, scratch,
                      g_xc + (size_t)t*NB*NCIT*DIN, g_fxc + (size_t)t*NB*NCIT*GF, g_hc,
                      bid - NBLK_S, NBLK_C, (NB*NCIT) >> 6, 1 + t,
                      nullptr, nullptr, nullptr, nullptr, NCIT, 0);
        gbar();
    }

    // ---- pred loop (24 steps) ----
    #pragma unroll 1
    for (int s = 0; s < TP; s++) {
        int tt = TH + s;
        stageA_phase(P.features, P.c_features, tt);
        gbar();
        stageB_phase();
        gbar();
        if (!isC)
            cheb_phase(scratch, g_xs, g_Lxs, P.conv_w, P.conv_b, g_xgs,
                       bid, NBLK_S, (NB*NSTA) >> 6);
        else
            cheb_phase(scratch, g_xc, g_Lxc, P.c_conv_w, P.c_conv_b, g_xgc,
                       bid - NBLK_S, NBLK_C, (NB*NCIT) >> 6);
        gbar();
        if (!isC)
            zgemm_phase(scratch, g_xgs, P.s2c_w, g_zs, bid, NBLK_S, (NB*NSTA) >> 6);
        else
            zgemm_phase(scratch, g_xgc, P.c2s_w, g_zc, bid - NBLK_S, NBLK_C, (NB*NCIT) >> 6);
        gbar();
        scatter_phase(P.c2s_b, P.s2c_b);
        gbar();
        if (!isC)
            gru_phase(swi, swh, sbi, sbh, scratch,
                      g_xs, g_fxs, g_hs, bid, NBLK_S, (NB*NSTA) >> 6, tt,
                      P.fc_w, P.fc_b, g_ys, P.out_s, NSTA, s);
        else
            gru_phase(swi, swh, sbi, sbh, scratch,
                      g_xc, g_fxc, g_hc, bid - NBLK_S, NBLK_C, (NB*NCIT) >> 6, tt,
                      P.c_fc_w, P.c_fc_b, g_yc, P.out_c, NCIT, s);
        gbar();
    }
}

// ---------------- host ----------------
static void* symaddr(const void* sym) {
    void* p = nullptr;
    cudaGetSymbolAddress(&p, sym);
    return p;
}

extern "C" void kernel_launch(void* const* d_in, const int* in_sizes, int n_in,
                              void* d_out, int out_size) {
    const float* x_hist     = (const float*)d_in[0];
    const float* features   = (const float*)d_in[1];
    const float* c_x_hist   = (const float*)d_in[2];
    const float* c_features = (const float*)d_in[3];
    const float* adj_sta    = (const float*)d_in[4];
    const float* adj_city   = (const float*)d_in[5];
    const float* afc        = (const float*)d_in[6];
    const float* conv_w     = (const float*)d_in[7];
    const float* conv_b     = (const float*)d_in[8];
    const float* c_conv_w   = (const float*)d_in[9];
    const float* c_conv_b   = (const float*)d_in[10];
    const float* gru_wi     = (const float*)d_in[11];
    const float* gru_wh     = (const float*)d_in[12];
    const float* gru_bi     = (const float*)d_in[13];
    const float* gru_bh     = (const float*)d_in[14];
    const float* c_gru_wi   = (const float*)d_in[15];
    const float* c_gru_wh   = (const float*)d_in[16];
    const float* c_gru_bi   = (const float*)d_in[17];
    const float* c_gru_bh   = (const float*)d_in[18];
    const float* fc_w       = (const float*)d_in[19];
    const float* fc_b       = (const float*)d_in[20];
    const float* c_fc_w     = (const float*)d_in[21];
    const float* c_fc_b     = (const float*)d_in[22];
    const float* c2s_w      = (const float*)d_in[23];
    const float* c2s_b      = (const float*)d_in[24];
    const float* s2c_w      = (const float*)d_in[25];
    const float* s2c_b      = (const float*)d_in[26];

    float* out_s = (float*)d_out;
    float* out_c = out_s + (size_t)NB * TP * NSTA;

    float* p_dinv_s     = (float*)symaddr(g_dinv_s);
    int*   p_cnt_s      = (int*)  symaddr(g_cnt_s);
    int*   p_Ls_rowptr  = (int*)  symaddr(g_Ls_rowptr);
    int*   p_Ls_cols    = (int*)  symaddr(g_Ls_cols);
    float* p_Ls_vals    = (float*)symaddr(g_Ls_vals);
    int*   p_cnt_afc    = (int*)  symaddr(g_cnt_afc);
    int*   p_afc_rowptr = (int*)  symaddr(g_afc_rowptr);
    int*   p_afc_cols   = (int*)  symaddr(g_afc_cols);
    int*   p_cnt_afcT   = (int*)  symaddr(g_cnt_afcT);
    int*   p_afcT_rowptr= (int*)  symaddr(g_afcT_rowptr);
    int*   p_afcT_cols  = (int*)  symaddr(g_afcT_cols);
    int*   p_cnt_c      = (int*)  symaddr(g_cnt_c);
    float* p_dinv_c     = (float*)symaddr(g_dinv_c);
    float* p_xs   = (float*)symaddr(g_xs);
    float* p_Lxs  = (float*)symaddr(g_Lxs);
    float* p_xgs  = (float*)symaddr(g_xgs);
    float* p_fxs  = (float*)symaddr(g_fxs);
    float* p_xc   = (float*)symaddr(g_xc);
    float* p_Lxc  = (float*)symaddr(g_Lxc);
    float* p_xgc  = (float*)symaddr(g_xgc);
    float* p_fxc  = (float*)symaddr(g_fxc);

    (void)in_sizes; (void)n_in; (void)out_size;

    const int mega_smem = MEGA_SMEM_FLOATS * (int)sizeof(float);
    cudaFuncSetAttribute(k_mega, cudaFuncAttributeMaxDynamicSharedMemorySize, mega_smem);
    const int cheb_smem = (56*64 + 56*64 + 64) * (int)sizeof(float);
    const int fuse_smem = (64*64 + 64 + 64*68) * (int)sizeof(float);

    // ---- preprocessing ----
    k_count_rows<<<NSTA, 128>>>(adj_sta, p_cnt_s, p_dinv_s, NSTA, NSTA, 1);
    k_scan<<<1, 1024>>>(p_cnt_s, p_Ls_rowptr, NSTA);
    k_fill_csr<<<(NSTA+3)/4, 128>>>(adj_sta, p_Ls_rowptr, p_Ls_cols, p_Ls_vals, p_dinv_s, NSTA, NSTA, 1);

    k_count_rows<<<NSTA, 128>>>(afc, p_cnt_afc, nullptr, NSTA, NCIT, 0);
    k_scan<<<1, 1024>>>(p_cnt_afc, p_afc_rowptr, NSTA);
    k_fill_csr<<<(NSTA+3)/4, 128>>>(afc, p_afc_rowptr, p_afc_cols, nullptr, nullptr, NSTA, NCIT, 0);

    k_count_cols<<<NCIT, 128>>>(afc, p_cnt_afcT, NSTA, NCIT);
    k_scan<<<1, 1024>>>(p_cnt_afcT, p_afcT_rowptr, NCIT);
    k_fill_csrT<<<(NCIT+3)/4, 128>>>(afc, p_afcT_rowptr, p_afcT_cols, NSTA, NCIT);

    k_count_rows<<<NCIT, 128>>>(adj_city, p_cnt_c, p_dinv_c, NCIT, NCIT, 1);
    k_fill_Lc<<<NCIT, NCIT>>>(adj_city);

    // ---- history (batched over 7 steps) ----
    {
        int tot = THIST*NB*NSTA*DIN + THIST*NB*NCIT*DIN;
        k_build_hist_x<<<(tot+255)/256, 256>>>(x_hist, features, c_x_hist, c_features);
    }
    k_spmm_hist<<<(NSTA*THIST*NB + 3)/4, 128>>>(THIST*NB);
    k_lmm_hist<<<(THIST*NB*NCIT*DIN + 255)/256, 256>>>(THIST*NB);
    {
        int ntS = (THIST*NB*NSTA) / 64, ntC = (THIST*NB*NCIT) / 64;
        k_cheb2<<<ntS + ntC, 256, cheb_smem>>>(p_xs, p_Lxs, conv_w, conv_b, p_xgs, ntS,
                                               p_xc, p_Lxc, c_conv_w, c_conv_b, p_xgc, ntC, ntS);
        k_fuse2<<<ntS + ntC, 256, fuse_smem>>>(p_xgs, p_xgc, c2s_w, c2s_b, p_fxs, ntS,
                                               s2c_w, s2c_b, p_fxc, ntC, ntS);
    }

    // ---- megakernel: h-init + history GRU + full autoregressive loop ----
    MegaP P;
    P.features = features; P.c_features = c_features;
    P.x_hist = x_hist; P.c_x_hist = c_x_hist;
    P.gwi_s = gru_wi; P.gwh_s = gru_wh; P.gbi_s = gru_bi; P.gbh_s = gru_bh;
    P.gwi_c = c_gru_wi; P.gwh_c = c_gru_wh; P.gbi_c = c_gru_bi; P.gbh_c = c_gru_bh;
    P.conv_w = conv_w; P.conv_b = conv_b; P.c_conv_w = c_conv_w; P.c_conv_b = c_conv_b;
    P.c2s_w = c2s_w; P.c2s_b = c2s_b; P.s2c_w = s2c_w; P.s2c_b = s2c_b;
    P.fc_w = fc_w; P.fc_b = fc_b; P.c_fc_w = c_fc_w; P.c_fc_b = c_fc_b;
    P.out_s = out_s; P.out_c = out_c;
    k_mega<<<NBLK, 256, mega_smem>>>(P);
}